// round 2
// baseline (speedup 1.0000x reference)
#include <cuda_runtime.h>
#include <math.h>

// Problem constants
#define BB    4
#define CC    768
#define LL    8192
#define NFFT  16384
#define EMB   33
#define ORD   64
#define FFT_NT 512

// Skewed shared-memory index to avoid bank conflicts at power-of-4 strides
#define SK(i) ((i) + ((i) >> 4))
#define DATA_SZ (NFFT + (NFFT >> 4))          // 17408 float2
#define TW_SZ   5461                          // sum of N/4^s for 7 radix-4 stages
#define FFT_SMEM ((DATA_SZ + TW_SZ) * (int)sizeof(float2))

// Static device scratch (allocation-free rule)
__device__ float  g_h3[LL * ORD];             // hidden after 3 sin layers  (2 MB)
__device__ float  g_k [CC * LL];              // modulated filter k[c,l]    (25 MB)
__device__ float2 g_KF[CC * NFFT];            // digit-reversed spectrum    (100 MB)

__device__ __forceinline__ float2 cadd(float2 a, float2 b){ return make_float2(a.x+b.x, a.y+b.y); }
__device__ __forceinline__ float2 csub(float2 a, float2 b){ return make_float2(a.x-b.x, a.y-b.y); }
__device__ __forceinline__ float2 cmul(float2 a, float2 b){
    return make_float2(a.x*b.x - a.y*b.y, a.x*b.y + a.y*b.x);
}

// Fill per-stage twiddle tables: stage s (L = N>>2s) holds w_L^j = exp(-2*pi*i*j/L), j < L/4.
// Stored stage-contiguous so warp reads are consecutive (conflict-free).
__device__ void fill_tw(float2* tw, int tid) {
    int off = 0;
    #pragma unroll
    for (int s = 0; s < 7; ++s) {
        int Ls = NFFT >> (2*s);
        int q  = Ls >> 2;
        float sc = 2.0f / (float)Ls;
        for (int j = tid; j < q; j += FFT_NT) {
            float sn, cs;
            sincospif(sc * (float)j, &sn, &cs);
            tw[off + j] = make_float2(cs, -sn);
        }
        off += q;
    }
}

// Forward radix-4 DIF. In-place on skewed smem, output in base-4 digit-reversed order.
__device__ void fft_dif(float2* d, const float2* tw, int tid) {
    int off = 0;
    #pragma unroll
    for (int s = 0; s < 7; ++s) {
        int shift = 12 - 2*s;
        int q = 1 << shift;
        for (int b = tid; b < (NFFT >> 2); b += FFT_NT) {
            int j    = b & (q - 1);
            int base = ((b >> shift) << (shift + 2)) | j;
            float2 c0 = d[SK(base)];
            float2 c1 = d[SK(base +   q)];
            float2 c2 = d[SK(base + 2*q)];
            float2 c3 = d[SK(base + 3*q)];
            float2 t0 = cadd(c0, c2), t1 = csub(c0, c2);
            float2 t2 = cadd(c1, c3), t3 = csub(c1, c3);
            float2 u1 = make_float2(t1.x + t3.y, t1.y - t3.x);  // t1 - i*t3
            float2 u3 = make_float2(t1.x - t3.y, t1.y + t3.x);  // t1 + i*t3
            float2 w1 = tw[off + j];
            float2 w2 = cmul(w1, w1);
            float2 w3 = cmul(w1, w2);
            d[SK(base)]         = cadd(t0, t2);
            d[SK(base +   q)]   = cmul(u1, w1);
            d[SK(base + 2*q)]   = cmul(csub(t0, t2), w2);
            d[SK(base + 3*q)]   = cmul(u3, w3);
        }
        off += q;
        __syncthreads();
    }
}

// Inverse radix-4 DIT: exact per-stage inverse of fft_dif applied in reverse order.
// Consumes digit-reversed data, produces natural order, scaled by NFFT (folded into g_KF).
__device__ void fft_dit_inv(float2* d, const float2* tw, int tid) {
    int offs[7];
    {
        int o = 0;
        #pragma unroll
        for (int s = 0; s < 7; ++s) { offs[s] = o; o += 1 << (12 - 2*s); }
    }
    #pragma unroll
    for (int s = 6; s >= 0; --s) {
        int shift = 12 - 2*s;
        int q = 1 << shift;
        int off = offs[s];
        for (int b = tid; b < (NFFT >> 2); b += FFT_NT) {
            int j    = b & (q - 1);
            int base = ((b >> shift) << (shift + 2)) | j;
            float2 w  = tw[off + j];
            float2 w1 = make_float2(w.x, -w.y);       // conj
            float2 w2 = cmul(w1, w1);
            float2 w3 = cmul(w1, w2);
            float2 y0 = d[SK(base)];
            float2 y1 = cmul(d[SK(base +   q)], w1);
            float2 y2 = cmul(d[SK(base + 2*q)], w2);
            float2 y3 = cmul(d[SK(base + 3*q)], w3);
            float2 t0 = cadd(y0, y2), t1 = csub(y0, y2);
            float2 t2 = cadd(y1, y3), t3 = csub(y1, y3);
            d[SK(base)]         = cadd(t0, t2);
            d[SK(base +   q)]   = make_float2(t1.x - t3.y, t1.y + t3.x);  // t1 + i*t3
            d[SK(base + 2*q)]   = csub(t0, t2);
            d[SK(base + 3*q)]   = make_float2(t1.x + t3.y, t1.y - t3.x);  // t1 - i*t3
        }
        __syncthreads();
    }
}

// ---------------- Kernel 1: implicit MLP hidden layers (3x Dense+Sin) -------------
// 64 threads (one per hidden unit), 16 sequence positions per block.
__global__ void mlp_hidden_kernel(const float* __restrict__ z,
                                  const float* __restrict__ W0, const float* __restrict__ b0,
                                  const float* __restrict__ W1, const float* __restrict__ b1,
                                  const float* __restrict__ W2, const float* __restrict__ b2,
                                  const float* __restrict__ freq) {
    __shared__ float sW0[EMB * ORD];
    __shared__ float sW1[ORD * ORD];
    __shared__ float sW2[ORD * ORD];
    __shared__ float sz[EMB + 1];
    __shared__ float sh1[ORD];
    __shared__ float sh2[ORD];

    int o = threadIdx.x;
    for (int i = o; i < EMB * ORD; i += ORD) sW0[i] = W0[i];
    for (int i = o; i < ORD * ORD; i += ORD) sW1[i] = W1[i];
    for (int i = o; i < ORD * ORD; i += ORD) sW2[i] = W2[i];
    float fb0 = b0[o], fb1 = b1[o], fb2 = b2[o], fq = freq[o];
    __syncthreads();

    int l0 = blockIdx.x * 16;
    for (int il = 0; il < 16; ++il) {
        int l = l0 + il;
        if (o < EMB) sz[o] = z[l * EMB + o];
        __syncthreads();
        float acc = fb0;
        #pragma unroll
        for (int e = 0; e < EMB; ++e) acc += sz[e] * sW0[e * ORD + o];
        float h1 = sinf(fq * acc);
        sh1[o] = h1;
        __syncthreads();
        acc = fb1;
        #pragma unroll 8
        for (int i = 0; i < ORD; ++i) acc += sh1[i] * sW1[i * ORD + o];
        float h2 = sinf(fq * acc);
        sh2[o] = h2;
        __syncthreads();
        acc = fb2;
        #pragma unroll 8
        for (int i = 0; i < ORD; ++i) acc += sh2[i] * sW2[i * ORD + o];
        g_h3[l * ORD + o] = sinf(fq * acc);
        __syncthreads();
    }
}

// ---------------- Kernel 2: output projection + exponential modulation ------------
// 256 blocks x 256 threads. Block: 32 l-positions, all 768 channels (6 chunks of 128).
__global__ void proj_kernel(const float* __restrict__ Wout,
                            const float* __restrict__ deltas) {
    __shared__ float4 sH4[32 * 17];   // h3 tile [32][68] padded
    __shared__ float4 sW4[64 * 32];   // Wout chunk [64][128]
    float* sH = (float*)sH4;
    float* sW = (float*)sW4;

    int tid = threadIdx.x;
    int lt  = blockIdx.x * 32;

    for (int idx = tid; idx < 32 * ORD; idx += 256) {
        int l_ = idx >> 6, o = idx & 63;
        sH[l_ * 68 + o] = g_h3[(lt + l_) * ORD + o];
    }
    __syncthreads();

    int ll = tid & 31;      // lane -> l (coalesced stores)
    int cq = tid >> 5;      // 0..7, owns 16 consecutive channels per chunk
    float hreg[ORD];
    {
        const float4* row = (const float4*)(sH + ll * 68);
        #pragma unroll
        for (int i = 0; i < 16; ++i) {
            float4 t = row[i];
            hreg[4*i] = t.x; hreg[4*i+1] = t.y; hreg[4*i+2] = t.z; hreg[4*i+3] = t.w;
        }
    }
    float tl = (float)(lt + ll) * (1.0f / (float)(LL - 1));

    for (int ch = 0; ch < 6; ++ch) {
        int c0 = ch * 128;
        __syncthreads();
        for (int idx = tid; idx < ORD * 128; idx += 256) {
            int o = idx >> 7, cc = idx & 127;
            sW[o * 128 + cc] = Wout[o * CC + c0 + cc];
        }
        __syncthreads();

        float acc[16];
        #pragma unroll
        for (int j = 0; j < 16; ++j) acc[j] = 0.0f;
        #pragma unroll 8
        for (int o = 0; o < ORD; ++o) {
            float h = hreg[o];
            const float4* row = sW4 + o * 32 + cq * 4;
            #pragma unroll
            for (int j = 0; j < 4; ++j) {
                float4 w = row[j];
                acc[4*j+0] += h * w.x;
                acc[4*j+1] += h * w.y;
                acc[4*j+2] += h * w.z;
                acc[4*j+3] += h * w.w;
            }
        }
        #pragma unroll
        for (int j = 0; j < 16; ++j) {
            int c = c0 + cq * 16 + j;
            float m = expf(-tl * fabsf(deltas[c]));
            g_k[c * LL + lt + ll] = acc[j] * m;
        }
    }
}

// ---------------- Kernel 3: per-channel filter spectrum (digit-reversed, /NFFT) ---
__global__ void __launch_bounds__(FFT_NT, 1) kf_fft_kernel() {
    extern __shared__ float2 sm[];
    float2* data = sm;
    float2* tw   = sm + DATA_SZ;
    int tid = threadIdx.x;
    int c   = blockIdx.x;

    fill_tw(tw, tid);
    const float* krow = g_k + c * LL;
    for (int i = tid; i < NFFT; i += FFT_NT) {
        float v = (i < LL) ? krow[i] : 0.0f;
        data[SK(i)] = make_float2(v, 0.0f);
    }
    __syncthreads();
    fft_dif(data, tw, tid);
    const float sc = 1.0f / (float)NFFT;
    for (int i = tid; i < NFFT; i += FFT_NT) {
        float2 v = data[SK(i)];
        g_KF[c * NFFT + i] = make_float2(v.x * sc, v.y * sc);
    }
}

// ---------------- Kernel 4: batched FFT convolution (2 batches packed as complex) --
__global__ void __launch_bounds__(FFT_NT, 1) conv_fft_kernel(const float* __restrict__ x,
                                                             const float* __restrict__ bias,
                                                             float* __restrict__ out) {
    extern __shared__ float2 sm[];
    float2* data = sm;
    float2* tw   = sm + DATA_SZ;
    int tid = threadIdx.x;
    int c = blockIdx.x;
    int p = blockIdx.y;

    const float* x0 = x + ((size_t)(2*p)   * CC + c) * LL;
    const float* x1 = x + ((size_t)(2*p+1) * CC + c) * LL;

    fill_tw(tw, tid);
    for (int i = tid; i < NFFT; i += FFT_NT) {
        float a = (i < LL) ? x0[i] : 0.0f;
        float b = (i < LL) ? x1[i] : 0.0f;
        data[SK(i)] = make_float2(a, b);
    }
    __syncthreads();

    fft_dif(data, tw, tid);

    const float2* kf = g_KF + c * NFFT;
    for (int i = tid; i < NFFT; i += FFT_NT) {
        data[SK(i)] = cmul(data[SK(i)], kf[i]);
    }
    __syncthreads();

    fft_dit_inv(data, tw, tid);

    float bc = bias[c];
    float* o0 = out + ((size_t)(2*p)   * CC + c) * LL;
    float* o1 = out + ((size_t)(2*p+1) * CC + c) * LL;
    for (int l = tid; l < LL; l += FFT_NT) {
        float2 v = data[SK(l)];
        o0[l] = v.x + x0[l] * bc;
        o1[l] = v.y + x1[l] * bc;
    }
}

extern "C" void kernel_launch(void* const* d_in, const int* in_sizes, int n_in,
                              void* d_out, int out_size) {
    const float* x      = (const float*)d_in[0];
    const float* bias   = (const float*)d_in[1];
    const float* z      = (const float*)d_in[2];
    const float* deltas = (const float*)d_in[3];
    const float* W0     = (const float*)d_in[4];
    const float* b0     = (const float*)d_in[5];
    const float* W1     = (const float*)d_in[6];
    const float* b1     = (const float*)d_in[7];
    const float* W2     = (const float*)d_in[8];
    const float* b2     = (const float*)d_in[9];
    const float* freq   = (const float*)d_in[10];
    const float* Wout   = (const float*)d_in[11];
    float* out = (float*)d_out;

    cudaFuncSetAttribute(kf_fft_kernel,  cudaFuncAttributeMaxDynamicSharedMemorySize, FFT_SMEM);
    cudaFuncSetAttribute(conv_fft_kernel, cudaFuncAttributeMaxDynamicSharedMemorySize, FFT_SMEM);

    mlp_hidden_kernel<<<LL / 16, ORD>>>(z, W0, b0, W1, b1, W2, b2, freq);
    proj_kernel<<<LL / 32, 256>>>(Wout, deltas);
    kf_fft_kernel<<<CC, FFT_NT, FFT_SMEM>>>();
    conv_fft_kernel<<<dim3(CC, BB / 2), FFT_NT, FFT_SMEM>>>(x, bias, out);
}

// round 3
// speedup vs baseline: 2.2202x; 2.2202x over previous
#include <cuda_runtime.h>
#include <math.h>

// Problem constants
#define BB    4
#define CC    768
#define LL    8192
#define NFFT  16384
#define EMB   33
#define ORD   64
#define NT    1024
#define R2f   0.70710678118654752f

// Skewed shared-memory index to reduce bank conflicts at power-of-2 strides
#define SK(i) ((i) + ((i) >> 4))
#define DATA_SZ (NFFT + (NFFT >> 4))          // 17408 float2
#define TW_SZ   2340                          // 2048+256+32+4 radix-8 twiddles
#define FFT_SMEM ((DATA_SZ + TW_SZ) * (int)sizeof(float2))

// Static device scratch (allocation-free rule)
__device__ float  g_h3[LL * ORD];             // hidden after 3 sin layers
__device__ float  g_k [CC * LL];              // modulated filter k[c,l]
__device__ float2 g_KF[CC * NFFT];            // digit-reversed spectrum / NFFT

__device__ __forceinline__ float2 cadd(float2 a, float2 b){ return make_float2(a.x+b.x, a.y+b.y); }
__device__ __forceinline__ float2 csub(float2 a, float2 b){ return make_float2(a.x-b.x, a.y-b.y); }
__device__ __forceinline__ float2 cmul(float2 a, float2 b){
    return make_float2(a.x*b.x - a.y*b.y, a.x*b.y + a.y*b.x);
}

// Twiddle tables for 4 radix-8 stages: q = 2048,256,32,4 at offsets 0,2048,2304,2336.
// tw[off+j] = exp(-2*pi*i * j / (8q))
__device__ void fill_tw(float2* tw, int tid) {
    const int qs[4]   = {2048, 256, 32, 4};
    const int offs[4] = {0, 2048, 2304, 2336};
    #pragma unroll
    for (int s = 0; s < 4; ++s) {
        int q = qs[s];
        float sc = 1.0f / (4.0f * (float)q);   // angle in units of pi
        for (int j = tid; j < q; j += NT) {
            float sn, cs;
            sincospif(sc * (float)j, &sn, &cs);
            tw[offs[s] + j] = make_float2(cs, -sn);
        }
    }
}

// ---- forward radix-8 DIF stage (in-place, disjoint butterflies) ----
__device__ __forceinline__ void r8_fwd(float2* d, const float2* tw, int shift, int off, int tid) {
    int q = 1 << shift;
    for (int b = tid; b < (NFFT >> 3); b += NT) {
        int j    = b & (q - 1);
        int base = ((b >> shift) << (shift + 3)) | j;
        float2 a0 = d[SK(base)];
        float2 a1 = d[SK(base +   q)];
        float2 a2 = d[SK(base + 2*q)];
        float2 a3 = d[SK(base + 3*q)];
        float2 a4 = d[SK(base + 4*q)];
        float2 a5 = d[SK(base + 5*q)];
        float2 a6 = d[SK(base + 6*q)];
        float2 a7 = d[SK(base + 7*q)];
        // even/odd split
        float2 c0 = cadd(a0,a4), c1 = cadd(a1,a5), c2 = cadd(a2,a6), c3 = cadd(a3,a7);
        float2 e0 = csub(a0,a4), e1 = csub(a1,a5), e2 = csub(a2,a6), e3 = csub(a3,a7);
        // e_n *= w8^n  (w8 = exp(-i*pi/4))
        e1 = make_float2(R2f*(e1.x + e1.y), R2f*(e1.y - e1.x));
        e2 = make_float2(e2.y, -e2.x);
        e3 = make_float2(R2f*(e3.y - e3.x), -R2f*(e3.x + e3.y));
        // DFT4(c) -> even outputs
        float2 t0 = cadd(c0,c2), t1 = csub(c0,c2), t2 = cadd(c1,c3), t3 = csub(c1,c3);
        float2 E0 = cadd(t0,t2), E2 = csub(t0,t2);
        float2 E1 = make_float2(t1.x + t3.y, t1.y - t3.x);   // t1 - i t3
        float2 E3 = make_float2(t1.x - t3.y, t1.y + t3.x);   // t1 + i t3
        // DFT4(e) -> odd outputs
        t0 = cadd(e0,e2); t1 = csub(e0,e2); t2 = cadd(e1,e3); t3 = csub(e1,e3);
        float2 O0 = cadd(t0,t2), O2 = csub(t0,t2);
        float2 O1 = make_float2(t1.x + t3.y, t1.y - t3.x);
        float2 O3 = make_float2(t1.x - t3.y, t1.y + t3.x);
        // twiddles w^m
        float2 w  = tw[off + j];
        float2 w2 = cmul(w,w),  w3 = cmul(w2,w), w4 = cmul(w2,w2);
        float2 w5 = cmul(w3,w2), w6 = cmul(w3,w3), w7 = cmul(w4,w3);
        d[SK(base)]        = E0;
        d[SK(base +   q)]  = cmul(O0, w);
        d[SK(base + 2*q)]  = cmul(E1, w2);
        d[SK(base + 3*q)]  = cmul(O1, w3);
        d[SK(base + 4*q)]  = cmul(E2, w4);
        d[SK(base + 5*q)]  = cmul(O2, w5);
        d[SK(base + 6*q)]  = cmul(E3, w6);
        d[SK(base + 7*q)]  = cmul(O3, w7);
    }
    __syncthreads();
}

// ---- final forward radix-4 stage (q=1, twiddle = 1) ----
__device__ __forceinline__ void r4_fwd(float2* d, int tid) {
    for (int b = tid; b < (NFFT >> 2); b += NT) {
        int base = b << 2;
        float2 a0 = d[SK(base)], a1 = d[SK(base+1)], a2 = d[SK(base+2)], a3 = d[SK(base+3)];
        float2 t0 = cadd(a0,a2), t1 = csub(a0,a2), t2 = cadd(a1,a3), t3 = csub(a1,a3);
        d[SK(base)]   = cadd(t0,t2);
        d[SK(base+1)] = make_float2(t1.x + t3.y, t1.y - t3.x);   // t1 - i t3
        d[SK(base+2)] = csub(t0,t2);
        d[SK(base+3)] = make_float2(t1.x - t3.y, t1.y + t3.x);   // t1 + i t3
    }
    __syncthreads();
}

// ---- first inverse stage (radix-4, q=1) fused with pointwise Kf multiply ----
__device__ __forceinline__ void r4_inv_pw(float2* d, const float2* __restrict__ kf, int tid) {
    for (int b = tid; b < (NFFT >> 2); b += NT) {
        int base = b << 2;
        const float4* kf4 = (const float4*)(kf + base);
        float4 k01 = kf4[0], k23 = kf4[1];
        float2 y0 = cmul(d[SK(base)],   make_float2(k01.x, k01.y));
        float2 y1 = cmul(d[SK(base+1)], make_float2(k01.z, k01.w));
        float2 y2 = cmul(d[SK(base+2)], make_float2(k23.x, k23.y));
        float2 y3 = cmul(d[SK(base+3)], make_float2(k23.z, k23.w));
        float2 t0 = cadd(y0,y2), t1 = csub(y0,y2), t2 = cadd(y1,y3), t3 = csub(y1,y3);
        d[SK(base)]   = cadd(t0,t2);
        d[SK(base+1)] = make_float2(t1.x - t3.y, t1.y + t3.x);   // t1 + i t3
        d[SK(base+2)] = csub(t0,t2);
        d[SK(base+3)] = make_float2(t1.x + t3.y, t1.y - t3.x);   // t1 - i t3
    }
    __syncthreads();
}

// ---- inverse radix-8 stage: exact per-stage inverse of r8_fwd ----
__device__ __forceinline__ void r8_inv(float2* d, const float2* tw, int shift, int off, int tid) {
    int q = 1 << shift;
    for (int b = tid; b < (NFFT >> 3); b += NT) {
        int j    = b & (q - 1);
        int base = ((b >> shift) << (shift + 3)) | j;
        float2 w = tw[off + j];
        w.y = -w.y;                                              // conj
        float2 w2 = cmul(w,w),  w3 = cmul(w2,w), w4 = cmul(w2,w2);
        float2 w5 = cmul(w3,w2), w6 = cmul(w3,w3), w7 = cmul(w4,w3);
        float2 A0 = d[SK(base)];
        float2 A1 = cmul(d[SK(base +   q)], w);
        float2 A2 = cmul(d[SK(base + 2*q)], w2);
        float2 A3 = cmul(d[SK(base + 3*q)], w3);
        float2 A4 = cmul(d[SK(base + 4*q)], w4);
        float2 A5 = cmul(d[SK(base + 5*q)], w5);
        float2 A6 = cmul(d[SK(base + 6*q)], w6);
        float2 A7 = cmul(d[SK(base + 7*q)], w7);
        // P = IDFT4(A0,A2,A4,A6)
        float2 t0 = cadd(A0,A4), t1 = csub(A0,A4), t2 = cadd(A2,A6), t3 = csub(A2,A6);
        float2 P0 = cadd(t0,t2), P2 = csub(t0,t2);
        float2 P1 = make_float2(t1.x - t3.y, t1.y + t3.x);       // t1 + i t3
        float2 P3 = make_float2(t1.x + t3.y, t1.y - t3.x);       // t1 - i t3
        // Q = IDFT4(A1,A3,A5,A7)
        t0 = cadd(A1,A5); t1 = csub(A1,A5); t2 = cadd(A3,A7); t3 = csub(A3,A7);
        float2 Q0 = cadd(t0,t2), Q2 = csub(t0,t2);
        float2 Q1 = make_float2(t1.x - t3.y, t1.y + t3.x);
        float2 Q3 = make_float2(t1.x + t3.y, t1.y - t3.x);
        // Q_n *= v^n, v = exp(+i*pi/4)
        Q1 = make_float2(R2f*(Q1.x - Q1.y),  R2f*(Q1.x + Q1.y));
        Q2 = make_float2(-Q2.y, Q2.x);
        Q3 = make_float2(-R2f*(Q3.x + Q3.y), R2f*(Q3.x - Q3.y));
        d[SK(base)]        = cadd(P0,Q0);
        d[SK(base +   q)]  = cadd(P1,Q1);
        d[SK(base + 2*q)]  = cadd(P2,Q2);
        d[SK(base + 3*q)]  = cadd(P3,Q3);
        d[SK(base + 4*q)]  = csub(P0,Q0);
        d[SK(base + 5*q)]  = csub(P1,Q1);
        d[SK(base + 6*q)]  = csub(P2,Q2);
        d[SK(base + 7*q)]  = csub(P3,Q3);
    }
    __syncthreads();
}

__device__ __forceinline__ void fwd_fft(float2* d, const float2* tw, int tid) {
    r8_fwd(d, tw, 11, 0,    tid);
    r8_fwd(d, tw,  8, 2048, tid);
    r8_fwd(d, tw,  5, 2304, tid);
    r8_fwd(d, tw,  2, 2336, tid);
    r4_fwd(d, tid);
}

// ---------------- Kernel 1: implicit MLP hidden layers (3x Dense+Sin) -------------
__global__ void mlp_hidden_kernel(const float* __restrict__ z,
                                  const float* __restrict__ W0, const float* __restrict__ b0,
                                  const float* __restrict__ W1, const float* __restrict__ b1,
                                  const float* __restrict__ W2, const float* __restrict__ b2,
                                  const float* __restrict__ freq) {
    __shared__ float sW0[EMB * ORD];
    __shared__ float sW1[ORD * ORD];
    __shared__ float sW2[ORD * ORD];
    __shared__ float sz[EMB + 1];
    __shared__ float sh1[ORD];
    __shared__ float sh2[ORD];

    int o = threadIdx.x;
    for (int i = o; i < EMB * ORD; i += ORD) sW0[i] = W0[i];
    for (int i = o; i < ORD * ORD; i += ORD) sW1[i] = W1[i];
    for (int i = o; i < ORD * ORD; i += ORD) sW2[i] = W2[i];
    float fb0 = b0[o], fb1 = b1[o], fb2 = b2[o], fq = freq[o];
    __syncthreads();

    int l0 = blockIdx.x * 16;
    for (int il = 0; il < 16; ++il) {
        int l = l0 + il;
        if (o < EMB) sz[o] = z[l * EMB + o];
        __syncthreads();
        float acc = fb0;
        #pragma unroll
        for (int e = 0; e < EMB; ++e) acc += sz[e] * sW0[e * ORD + o];
        sh1[o] = sinf(fq * acc);
        __syncthreads();
        acc = fb1;
        #pragma unroll 8
        for (int i = 0; i < ORD; ++i) acc += sh1[i] * sW1[i * ORD + o];
        sh2[o] = sinf(fq * acc);
        __syncthreads();
        acc = fb2;
        #pragma unroll 8
        for (int i = 0; i < ORD; ++i) acc += sh2[i] * sW2[i * ORD + o];
        g_h3[l * ORD + o] = sinf(fq * acc);
        __syncthreads();
    }
}

// ---------------- Kernel 2: output projection + exponential modulation ------------
__global__ void proj_kernel(const float* __restrict__ Wout,
                            const float* __restrict__ deltas) {
    __shared__ float4 sH4[32 * 17];
    __shared__ float4 sW4[64 * 32];
    float* sH = (float*)sH4;
    float* sW = (float*)sW4;

    int tid = threadIdx.x;
    int lt  = blockIdx.x * 32;

    for (int idx = tid; idx < 32 * ORD; idx += 256) {
        int l_ = idx >> 6, o = idx & 63;
        sH[l_ * 68 + o] = g_h3[(lt + l_) * ORD + o];
    }
    __syncthreads();

    int ll = tid & 31;
    int cq = tid >> 5;
    float hreg[ORD];
    {
        const float4* row = (const float4*)(sH + ll * 68);
        #pragma unroll
        for (int i = 0; i < 16; ++i) {
            float4 t = row[i];
            hreg[4*i] = t.x; hreg[4*i+1] = t.y; hreg[4*i+2] = t.z; hreg[4*i+3] = t.w;
        }
    }
    float tl = (float)(lt + ll) * (1.0f / (float)(LL - 1));

    for (int ch = 0; ch < 6; ++ch) {
        int c0 = ch * 128;
        __syncthreads();
        for (int idx = tid; idx < ORD * 128; idx += 256) {
            int o = idx >> 7, cc = idx & 127;
            sW[o * 128 + cc] = Wout[o * CC + c0 + cc];
        }
        __syncthreads();

        float acc[16];
        #pragma unroll
        for (int j = 0; j < 16; ++j) acc[j] = 0.0f;
        #pragma unroll 8
        for (int o = 0; o < ORD; ++o) {
            float h = hreg[o];
            const float4* row = sW4 + o * 32 + cq * 4;
            #pragma unroll
            for (int j = 0; j < 4; ++j) {
                float4 w = row[j];
                acc[4*j+0] += h * w.x;
                acc[4*j+1] += h * w.y;
                acc[4*j+2] += h * w.z;
                acc[4*j+3] += h * w.w;
            }
        }
        #pragma unroll
        for (int j = 0; j < 16; ++j) {
            int c = c0 + cq * 16 + j;
            float m = expf(-tl * fabsf(deltas[c]));
            g_k[c * LL + lt + ll] = acc[j] * m;
        }
    }
}

// ---------------- Kernel 3: filter spectra, two channels per FFT ------------------
// FFT of (k_c0 + i*k_c1); split via conjugate symmetry directly in digit-reversed
// storage. Scale 1/NFFT folded in.
__global__ void __launch_bounds__(NT, 1) kf_fft_kernel() {
    extern __shared__ float2 sm[];
    float2* data = sm;
    float2* tw   = sm + DATA_SZ;
    int tid = threadIdx.x;
    int c0  = blockIdx.x * 2;
    int c1  = c0 + 1;

    fill_tw(tw, tid);
    const float* k0 = g_k + (size_t)c0 * LL;
    const float* k1 = g_k + (size_t)c1 * LL;
    for (int i = tid; i < NFFT; i += NT) {
        float re = (i < LL) ? k0[i] : 0.0f;
        float im = (i < LL) ? k1[i] : 0.0f;
        data[SK(i)] = make_float2(re, im);
    }
    __syncthreads();

    fwd_fft(data, tw, tid);

    const float s = 0.5f / (float)NFFT;
    float2* KF0 = g_KF + (size_t)c0 * NFFT;
    float2* KF1 = g_KF + (size_t)c1 * NFFT;
    for (int p = tid; p < NFFT; p += NT) {
        // natural frequency index of digit-reversed position p (radices 8,8,8,8,4)
        int j  = (p >> 11) | (((p >> 8) & 7) << 3) | (((p >> 5) & 7) << 6)
               | (((p >> 2) & 7) << 9) | ((p & 3) << 12);
        int jn = (NFFT - j) & (NFFT - 1);
        int pp = ((jn & 7) << 11) | (((jn >> 3) & 7) << 8) | (((jn >> 6) & 7) << 5)
               | (((jn >> 9) & 7) << 2) | ((jn >> 12) & 3);
        float2 z1 = data[SK(p)];
        float2 z2 = data[SK(pp)];
        KF0[p] = make_float2(s * (z1.x + z2.x), s * (z1.y - z2.y));
        KF1[p] = make_float2(s * (z1.y + z2.y), s * (z2.x - z1.x));
    }
}

// ---------------- Kernel 4: batched FFT convolution (2 batches as one complex) ----
__global__ void __launch_bounds__(NT, 1) conv_fft_kernel(const float* __restrict__ x,
                                                         const float* __restrict__ bias,
                                                         float* __restrict__ out) {
    extern __shared__ float2 sm[];
    float2* data = sm;
    float2* tw   = sm + DATA_SZ;
    int tid = threadIdx.x;
    int c = blockIdx.x;
    int p = blockIdx.y;

    const float* x0 = x + ((size_t)(2*p)   * CC + c) * LL;
    const float* x1 = x + ((size_t)(2*p+1) * CC + c) * LL;

    fill_tw(tw, tid);
    for (int i = tid; i < NFFT; i += NT) {
        float a = (i < LL) ? x0[i] : 0.0f;
        float b = (i < LL) ? x1[i] : 0.0f;
        data[SK(i)] = make_float2(a, b);
    }
    __syncthreads();

    fwd_fft(data, tw, tid);

    // inverse (first stage fused with pointwise Kf multiply)
    const float2* kf = g_KF + (size_t)c * NFFT;
    r4_inv_pw(data, kf, tid);
    r8_inv(data, tw,  2, 2336, tid);
    r8_inv(data, tw,  5, 2304, tid);
    r8_inv(data, tw,  8, 2048, tid);
    r8_inv(data, tw, 11, 0,    tid);

    float bc = bias[c];
    float* o0 = out + ((size_t)(2*p)   * CC + c) * LL;
    float* o1 = out + ((size_t)(2*p+1) * CC + c) * LL;
    for (int l = tid; l < LL; l += NT) {
        float2 v = data[SK(l)];
        o0[l] = v.x + x0[l] * bc;
        o1[l] = v.y + x1[l] * bc;
    }
}

extern "C" void kernel_launch(void* const* d_in, const int* in_sizes, int n_in,
                              void* d_out, int out_size) {
    const float* x      = (const float*)d_in[0];
    const float* bias   = (const float*)d_in[1];
    const float* z      = (const float*)d_in[2];
    const float* deltas = (const float*)d_in[3];
    const float* W0     = (const float*)d_in[4];
    const float* b0     = (const float*)d_in[5];
    const float* W1     = (const float*)d_in[6];
    const float* b1     = (const float*)d_in[7];
    const float* W2     = (const float*)d_in[8];
    const float* b2     = (const float*)d_in[9];
    const float* freq   = (const float*)d_in[10];
    const float* Wout   = (const float*)d_in[11];
    float* out = (float*)d_out;

    cudaFuncSetAttribute(kf_fft_kernel,   cudaFuncAttributeMaxDynamicSharedMemorySize, FFT_SMEM);
    cudaFuncSetAttribute(conv_fft_kernel, cudaFuncAttributeMaxDynamicSharedMemorySize, FFT_SMEM);

    mlp_hidden_kernel<<<LL / 16, ORD>>>(z, W0, b0, W1, b1, W2, b2, freq);
    proj_kernel<<<LL / 32, 256>>>(Wout, deltas);
    kf_fft_kernel<<<CC / 2, NT, FFT_SMEM>>>();
    conv_fft_kernel<<<dim3(CC, BB / 2), NT, FFT_SMEM>>>(x, bias, out);
}

// round 4
// speedup vs baseline: 2.5059x; 1.1287x over previous
#include <cuda_runtime.h>
#include <math.h>

// Problem constants
#define BB    4
#define CC    768
#define LL    8192
#define NFFT  16384
#define EMB   33
#define ORD   64
#define NT    1024

#define C1f 0.923879532511287f   // cos(pi/8)
#define S1f 0.382683432365090f   // sin(pi/8)
#define R2f 0.707106781186548f   // sqrt(2)/2

// Skewed shared index: groups of 16 float2 stay contiguous & 16B-aligned
#define SK(i) ((i) + (((i) >> 4) << 1))
#define DATA_SZ 18432                         // SK(16383)=18429 < 18432
#define TW_SZ   1092                          // 1024 + 64 + 4
#define FFT_SMEM ((DATA_SZ + TW_SZ) * (int)sizeof(float2))

// Static device scratch (allocation-free rule)
__device__ float  g_h3[LL * ORD];
__device__ float  g_k [CC * LL];
__device__ float2 g_KF[CC * NFFT];            // digit-reversed spectrum / NFFT

__device__ __forceinline__ float2 cadd(float2 a, float2 b){ return make_float2(a.x+b.x, a.y+b.y); }
__device__ __forceinline__ float2 csub(float2 a, float2 b){ return make_float2(a.x-b.x, a.y-b.y); }
__device__ __forceinline__ float2 cmul(float2 a, float2 b){
    return make_float2(a.x*b.x - a.y*b.y, a.x*b.y + a.y*b.x);
}
__device__ __forceinline__ float2 cmulc(float2 a, float cr, float ci){
    return make_float2(a.x*cr - a.y*ci, a.x*ci + a.y*cr);
}
// a * (-i) and a * (+i)
__device__ __forceinline__ float2 mni(float2 a){ return make_float2(a.y, -a.x); }
__device__ __forceinline__ float2 mpi(float2 a){ return make_float2(-a.y, a.x); }

// After dft16/idft16, output index m lives at register slot OUTI(m)
#define OUTI(m) ((((m) & 3) << 2) | ((m) >> 2))

// Twiddle tables: q=1024 @0 (w=e^{-2pi i j/16384}), q=64 @1024, q=4 @1088
__device__ __forceinline__ void fill_tw(float2* tw, int tid) {
    float sn, cs;
    if (tid < 1024) {
        sincospif((float)tid * (1.0f/8192.0f), &sn, &cs);
        tw[tid] = make_float2(cs, -sn);
    }
    if (tid < 64) {
        sincospif((float)tid * (1.0f/512.0f), &sn, &cs);
        tw[1024 + tid] = make_float2(cs, -sn);
    }
    if (tid < 4) {
        sincospif((float)tid * (1.0f/32.0f), &sn, &cs);
        tw[1088 + tid] = make_float2(cs, -sn);
    }
}

// ---- DFT16 pieces (decomposition n=4c+d, m=r+4s; output X_m -> v[4r+s]) ----
__device__ __forceinline__ void dft16_tail(float2 v[16]) {
    // twiddles W16^{rd} on v[4r+d]
    v[5]  = cmulc(v[5],  C1f, -S1f);
    v[6]  = cmulc(v[6],  R2f, -R2f);
    v[7]  = cmulc(v[7],  S1f, -C1f);
    v[9]  = cmulc(v[9],  R2f, -R2f);
    v[10] = mni(v[10]);
    v[11] = cmulc(v[11], -R2f, -R2f);
    v[13] = cmulc(v[13], S1f, -C1f);
    v[14] = cmulc(v[14], -R2f, -R2f);
    v[15] = cmulc(v[15], -C1f, S1f);
    #pragma unroll
    for (int r = 0; r < 4; ++r) {
        float2 a = v[4*r], b = v[4*r+1], c = v[4*r+2], e = v[4*r+3];
        float2 u0 = cadd(a,c), u1 = csub(a,c), u2 = cadd(b,e), u3 = csub(b,e);
        v[4*r]   = cadd(u0,u2);
        v[4*r+1] = cadd(u1, mni(u3));
        v[4*r+2] = csub(u0,u2);
        v[4*r+3] = cadd(u1, mpi(u3));
    }
}
__device__ __forceinline__ void dft16(float2 v[16]) {
    #pragma unroll
    for (int dd = 0; dd < 4; ++dd) {
        float2 a = v[dd], b = v[4+dd], c = v[8+dd], e = v[12+dd];
        float2 t0 = cadd(a,c), t1 = csub(a,c), t2 = cadd(b,e), t3 = csub(b,e);
        v[dd]    = cadd(t0,t2);
        v[4+dd]  = cadd(t1, mni(t3));
        v[8+dd]  = csub(t0,t2);
        v[12+dd] = cadd(t1, mpi(t3));
    }
    dft16_tail(v);
}
__device__ __forceinline__ void idft16_cols_tw(float2 v[16]) {
    #pragma unroll
    for (int dd = 0; dd < 4; ++dd) {
        float2 a = v[dd], b = v[4+dd], c = v[8+dd], e = v[12+dd];
        float2 t0 = cadd(a,c), t1 = csub(a,c), t2 = cadd(b,e), t3 = csub(b,e);
        v[dd]    = cadd(t0,t2);
        v[4+dd]  = cadd(t1, mpi(t3));
        v[8+dd]  = csub(t0,t2);
        v[12+dd] = cadd(t1, mni(t3));
    }
    v[5]  = cmulc(v[5],  C1f, S1f);
    v[6]  = cmulc(v[6],  R2f, R2f);
    v[7]  = cmulc(v[7],  S1f, C1f);
    v[9]  = cmulc(v[9],  R2f, R2f);
    v[10] = mpi(v[10]);
    v[11] = cmulc(v[11], -R2f, R2f);
    v[13] = cmulc(v[13], S1f, C1f);
    v[14] = cmulc(v[14], -R2f, R2f);
    v[15] = cmulc(v[15], -C1f, -S1f);
}
__device__ __forceinline__ void idft16(float2 v[16]) {
    idft16_cols_tw(v);
    #pragma unroll
    for (int r = 0; r < 4; ++r) {
        float2 a = v[4*r], b = v[4*r+1], c = v[4*r+2], e = v[4*r+3];
        float2 u0 = cadd(a,c), u1 = csub(a,c), u2 = cadd(b,e), u3 = csub(b,e);
        v[4*r]   = cadd(u0,u2);
        v[4*r+1] = cadd(u1, mpi(u3));
        v[4*r+2] = csub(u0,u2);
        v[4*r+3] = cadd(u1, mni(u3));
    }
}

// ---- Stage F0: radix-16, q=1024, reads two zero-padded real rows from gmem ----
__device__ __forceinline__ void f0_fwd(float2* d, const float2* tw,
                                       const float* __restrict__ r0,
                                       const float* __restrict__ r1, int tid) {
    int j = tid;
    float2 v[16];
    #pragma unroll
    for (int dd = 0; dd < 4; ++dd) {
        int ia = j + (dd << 10);
        int ib = j + ((dd + 4) << 10);
        float2 a = make_float2(r0[ia], r1[ia]);
        float2 b = make_float2(r0[ib], r1[ib]);
        // DFT-4 over c with x[8+d]=x[12+d]=0
        v[dd]    = cadd(a, b);
        v[4+dd]  = cadd(a, mni(b));
        v[8+dd]  = csub(a, b);
        v[12+dd] = cadd(a, mpi(b));
    }
    dft16_tail(v);
    float2 w = tw[j];
    float2 wp = w;
    d[SK(j)] = v[0];
    #pragma unroll
    for (int m = 1; m < 16; ++m) {
        d[SK(j + (m << 10))] = cmul(v[OUTI(m)], wp);
        wp = cmul(wp, w);
    }
    __syncthreads();
}

// ---- Middle radix-16 stages ----
__device__ __forceinline__ void r16_fwd(float2* d, const float2* tw, int logq, int off, int tid) {
    int q = 1 << logq;
    int j = tid & (q - 1);
    int base = ((tid >> logq) << (logq + 4)) | j;
    float2 v[16];
    #pragma unroll
    for (int m = 0; m < 16; ++m) v[m] = d[SK(base + (m << logq))];
    dft16(v);
    float2 w = tw[off + j];
    float2 wp = w;
    d[SK(base)] = v[0];
    #pragma unroll
    for (int m = 1; m < 16; ++m) {
        d[SK(base + (m << logq))] = cmul(v[OUTI(m)], wp);
        wp = cmul(wp, w);
    }
    __syncthreads();
}
__device__ __forceinline__ void r16_inv(float2* d, const float2* tw, int logq, int off, int tid) {
    int q = 1 << logq;
    int j = tid & (q - 1);
    int base = ((tid >> logq) << (logq + 4)) | j;
    float2 w = tw[off + j]; w.y = -w.y;
    float2 v[16];
    v[0] = d[SK(base)];
    float2 wp = w;
    #pragma unroll
    for (int m = 1; m < 16; ++m) {
        v[m] = cmul(d[SK(base + (m << logq))], wp);
        wp = cmul(wp, w);
    }
    idft16(v);
    #pragma unroll
    for (int m = 0; m < 16; ++m) d[SK(base + (m << logq))] = v[OUTI(m)];
    __syncthreads();
}

// ---- Stage F3: final forward radix-4 (q=1), 16 consecutive elements via float4 ----
__device__ __forceinline__ void f3_fwd(float2* d, int tid) {
    int base = tid << 4;
    float4* p4 = (float4*)(d + SK(base));     // contiguous, 16B aligned
    float2 v[16];
    #pragma unroll
    for (int u = 0; u < 8; ++u) {
        float4 t = p4[u];
        v[2*u]   = make_float2(t.x, t.y);
        v[2*u+1] = make_float2(t.z, t.w);
    }
    #pragma unroll
    for (int k = 0; k < 4; ++k) {
        float2 a0 = v[4*k], a1 = v[4*k+1], a2 = v[4*k+2], a3 = v[4*k+3];
        float2 t0 = cadd(a0,a2), t1 = csub(a0,a2), t2 = cadd(a1,a3), t3 = csub(a1,a3);
        v[4*k]   = cadd(t0,t2);
        v[4*k+1] = cadd(t1, mni(t3));
        v[4*k+2] = csub(t0,t2);
        v[4*k+3] = cadd(t1, mpi(t3));
    }
    #pragma unroll
    for (int u = 0; u < 8; ++u)
        p4[u] = make_float4(v[2*u].x, v[2*u].y, v[2*u+1].x, v[2*u+1].y);
    __syncthreads();
}

// ---- Stage I0: pointwise Kf multiply fused with inverse radix-4 (q=1) ----
__device__ __forceinline__ void i0_inv_pw(float2* d, const float2* __restrict__ kf, int tid) {
    int base = tid << 4;
    float4* p4 = (float4*)(d + SK(base));
    const float4* k4 = (const float4*)(kf + base);
    float2 v[16];
    #pragma unroll
    for (int u = 0; u < 8; ++u) {
        float4 t  = p4[u];
        float4 kk = k4[u];
        v[2*u]   = cmul(make_float2(t.x, t.y), make_float2(kk.x, kk.y));
        v[2*u+1] = cmul(make_float2(t.z, t.w), make_float2(kk.z, kk.w));
    }
    #pragma unroll
    for (int k = 0; k < 4; ++k) {
        float2 a0 = v[4*k], a1 = v[4*k+1], a2 = v[4*k+2], a3 = v[4*k+3];
        float2 t0 = cadd(a0,a2), t1 = csub(a0,a2), t2 = cadd(a1,a3), t3 = csub(a1,a3);
        v[4*k]   = cadd(t0,t2);
        v[4*k+1] = cadd(t1, mpi(t3));
        v[4*k+2] = csub(t0,t2);
        v[4*k+3] = cadd(t1, mni(t3));
    }
    #pragma unroll
    for (int u = 0; u < 8; ++u)
        p4[u] = make_float4(v[2*u].x, v[2*u].y, v[2*u+1].x, v[2*u+1].y);
    __syncthreads();
}

// ---- Stage I3: inverse radix-16 q=1024, only outputs m<8, write gmem + bias ----
__device__ __forceinline__ void i3_store(const float2* d, const float2* tw,
                                         const float* __restrict__ x0,
                                         const float* __restrict__ x1,
                                         float* __restrict__ o0,
                                         float* __restrict__ o1,
                                         float bc, int tid) {
    int j = tid;
    float2 w = tw[j]; w.y = -w.y;
    float2 v[16];
    v[0] = d[SK(j)];
    float2 wp = w;
    #pragma unroll
    for (int m = 1; m < 16; ++m) {
        v[m] = cmul(d[SK(j + (m << 10))], wp);
        wp = cmul(wp, w);
    }
    idft16_cols_tw(v);
    #pragma unroll
    for (int r = 0; r < 4; ++r) {
        float2 a = v[4*r], b = v[4*r+1], c = v[4*r+2], e = v[4*r+3];
        float2 u0 = cadd(a,c), u1 = csub(a,c), u2 = cadd(b,e), u3 = csub(b,e);
        float2 y0 = cadd(u0,u2);              // s=0 -> m=r
        float2 y1 = cadd(u1, mpi(u3));        // s=1 -> m=r+4
        int i0 = j + (r << 10);
        int i1 = j + ((r + 4) << 10);
        o0[i0] = y0.x + x0[i0] * bc;  o1[i0] = y0.y + x1[i0] * bc;
        o0[i1] = y1.x + x0[i1] * bc;  o1[i1] = y1.y + x1[i1] * bc;
    }
}

// ---------------- Kernel 1: implicit MLP hidden layers (3x Dense+Sin) -------------
__global__ void mlp_hidden_kernel(const float* __restrict__ z,
                                  const float* __restrict__ W0, const float* __restrict__ b0,
                                  const float* __restrict__ W1, const float* __restrict__ b1,
                                  const float* __restrict__ W2, const float* __restrict__ b2,
                                  const float* __restrict__ freq) {
    __shared__ float sW0[EMB * ORD];
    __shared__ float sW1[ORD * ORD];
    __shared__ float sW2[ORD * ORD];
    __shared__ float sz[EMB + 1];
    __shared__ float sh1[ORD];
    __shared__ float sh2[ORD];

    int o = threadIdx.x;
    for (int i = o; i < EMB * ORD; i += ORD) sW0[i] = W0[i];
    for (int i = o; i < ORD * ORD; i += ORD) sW1[i] = W1[i];
    for (int i = o; i < ORD * ORD; i += ORD) sW2[i] = W2[i];
    float fb0 = b0[o], fb1 = b1[o], fb2 = b2[o], fq = freq[o];
    __syncthreads();

    int l0 = blockIdx.x * 4;
    for (int il = 0; il < 4; ++il) {
        int l = l0 + il;
        if (o < EMB) sz[o] = z[l * EMB + o];
        __syncthreads();
        float acc = fb0;
        #pragma unroll
        for (int e = 0; e < EMB; ++e) acc += sz[e] * sW0[e * ORD + o];
        sh1[o] = sinf(fq * acc);
        __syncthreads();
        acc = fb1;
        #pragma unroll 8
        for (int i = 0; i < ORD; ++i) acc += sh1[i] * sW1[i * ORD + o];
        sh2[o] = sinf(fq * acc);
        __syncthreads();
        acc = fb2;
        #pragma unroll 8
        for (int i = 0; i < ORD; ++i) acc += sh2[i] * sW2[i * ORD + o];
        g_h3[l * ORD + o] = sinf(fq * acc);
        __syncthreads();
    }
}

// ---------------- Kernel 2: output projection + exponential modulation ------------
__global__ void proj_kernel(const float* __restrict__ Wout,
                            const float* __restrict__ deltas) {
    __shared__ float4 sH4[32 * 17];
    __shared__ float4 sW4[64 * 32];
    float* sH = (float*)sH4;
    float* sW = (float*)sW4;

    int tid = threadIdx.x;
    int lt  = blockIdx.x * 32;

    for (int idx = tid; idx < 32 * ORD; idx += 256) {
        int l_ = idx >> 6, o = idx & 63;
        sH[l_ * 68 + o] = g_h3[(lt + l_) * ORD + o];
    }
    __syncthreads();

    int ll = tid & 31;
    int cq = tid >> 5;
    float hreg[ORD];
    {
        const float4* row = (const float4*)(sH + ll * 68);
        #pragma unroll
        for (int i = 0; i < 16; ++i) {
            float4 t = row[i];
            hreg[4*i] = t.x; hreg[4*i+1] = t.y; hreg[4*i+2] = t.z; hreg[4*i+3] = t.w;
        }
    }
    float tl = (float)(lt + ll) * (1.0f / (float)(LL - 1));

    for (int ch = 0; ch < 6; ++ch) {
        int c0 = ch * 128;
        __syncthreads();
        for (int idx = tid; idx < ORD * 128; idx += 256) {
            int o = idx >> 7, cc = idx & 127;
            sW[o * 128 + cc] = Wout[o * CC + c0 + cc];
        }
        __syncthreads();

        float acc[16];
        #pragma unroll
        for (int j = 0; j < 16; ++j) acc[j] = 0.0f;
        #pragma unroll 8
        for (int o = 0; o < ORD; ++o) {
            float h = hreg[o];
            const float4* row = sW4 + o * 32 + cq * 4;
            #pragma unroll
            for (int j = 0; j < 4; ++j) {
                float4 w = row[j];
                acc[4*j+0] += h * w.x;
                acc[4*j+1] += h * w.y;
                acc[4*j+2] += h * w.z;
                acc[4*j+3] += h * w.w;
            }
        }
        #pragma unroll
        for (int j = 0; j < 16; ++j) {
            int c = c0 + cq * 16 + j;
            float m = expf(-tl * fabsf(deltas[c]));
            g_k[c * LL + lt + ll] = acc[j] * m;
        }
    }
}

// ---------------- Kernel 3: filter spectra, two channels per FFT ------------------
__global__ void __launch_bounds__(NT, 1) kf_fft_kernel() {
    extern __shared__ float2 sm[];
    float2* data = sm;
    float2* tw   = sm + DATA_SZ;
    int tid = threadIdx.x;
    int c0  = blockIdx.x * 2;
    int c1  = c0 + 1;

    fill_tw(tw, tid);
    f0_fwd(data, tw, g_k + (size_t)c0 * LL, g_k + (size_t)c1 * LL, tid);
    r16_fwd(data, tw, 6, 1024, tid);
    r16_fwd(data, tw, 2, 1088, tid);
    f3_fwd(data, tid);

    const float s = 0.5f / (float)NFFT;
    float2* KF0 = g_KF + (size_t)c0 * NFFT;
    float2* KF1 = g_KF + (size_t)c1 * NFFT;
    for (int p = tid; p < NFFT; p += NT) {
        // natural freq index of digit-reversed position p (radices 16,16,16,4)
        int j  = (p >> 10) | (((p >> 6) & 15) << 4) | (((p >> 2) & 15) << 8) | ((p & 3) << 12);
        int jn = (NFFT - j) & (NFFT - 1);
        int pp = ((jn & 15) << 10) | (((jn >> 4) & 15) << 6) | (((jn >> 8) & 15) << 2) | (jn >> 12);
        float2 z1 = data[SK(p)];
        float2 z2 = data[SK(pp)];
        KF0[p] = make_float2(s * (z1.x + z2.x), s * (z1.y - z2.y));
        KF1[p] = make_float2(s * (z1.y + z2.y), s * (z2.x - z1.x));
    }
}

// ---------------- Kernel 4: batched FFT convolution (2 batches as one complex) ----
__global__ void __launch_bounds__(NT, 1) conv_fft_kernel(const float* __restrict__ x,
                                                         const float* __restrict__ bias,
                                                         float* __restrict__ out) {
    extern __shared__ float2 sm[];
    float2* data = sm;
    float2* tw   = sm + DATA_SZ;
    int tid = threadIdx.x;
    int c = blockIdx.x;
    int p = blockIdx.y;

    const float* x0 = x + ((size_t)(2*p)   * CC + c) * LL;
    const float* x1 = x + ((size_t)(2*p+1) * CC + c) * LL;

    fill_tw(tw, tid);
    f0_fwd(data, tw, x0, x1, tid);
    r16_fwd(data, tw, 6, 1024, tid);
    r16_fwd(data, tw, 2, 1088, tid);
    f3_fwd(data, tid);

    i0_inv_pw(data, g_KF + (size_t)c * NFFT, tid);
    r16_inv(data, tw, 2, 1088, tid);
    r16_inv(data, tw, 6, 1024, tid);

    float bc = bias[c];
    float* o0 = out + ((size_t)(2*p)   * CC + c) * LL;
    float* o1 = out + ((size_t)(2*p+1) * CC + c) * LL;
    i3_store(data, tw, x0, x1, o0, o1, bc, tid);
}

extern "C" void kernel_launch(void* const* d_in, const int* in_sizes, int n_in,
                              void* d_out, int out_size) {
    const float* x      = (const float*)d_in[0];
    const float* bias   = (const float*)d_in[1];
    const float* z      = (const float*)d_in[2];
    const float* deltas = (const float*)d_in[3];
    const float* W0     = (const float*)d_in[4];
    const float* b0     = (const float*)d_in[5];
    const float* W1     = (const float*)d_in[6];
    const float* b1     = (const float*)d_in[7];
    const float* W2     = (const float*)d_in[8];
    const float* b2     = (const float*)d_in[9];
    const float* freq   = (const float*)d_in[10];
    const float* Wout   = (const float*)d_in[11];
    float* out = (float*)d_out;

    cudaFuncSetAttribute(kf_fft_kernel,   cudaFuncAttributeMaxDynamicSharedMemorySize, FFT_SMEM);
    cudaFuncSetAttribute(conv_fft_kernel, cudaFuncAttributeMaxDynamicSharedMemorySize, FFT_SMEM);

    mlp_hidden_kernel<<<LL / 4, ORD>>>(z, W0, b0, W1, b1, W2, b2, freq);
    proj_kernel<<<LL / 32, 256>>>(Wout, deltas);
    kf_fft_kernel<<<CC / 2, NT, FFT_SMEM>>>();
    conv_fft_kernel<<<dim3(CC, BB / 2), NT, FFT_SMEM>>>(x, bias, out);
}

// round 5
// speedup vs baseline: 2.7638x; 1.1029x over previous
#include <cuda_runtime.h>
#include <math.h>

// Problem constants
#define BB    4
#define CC    768
#define LL    8192
#define NFFT  16384
#define EMB   33
#define ORD   64
#define NT    1024

#define C1f 0.923879532511287f   // cos(pi/8)
#define S1f 0.382683432365090f   // sin(pi/8)
#define R2f 0.707106781186548f   // sqrt(2)/2

// Skewed shared index: groups of 16 float2 stay contiguous & 16B-aligned
#define SK(i) ((i) + (((i) >> 4) << 1))
#define DATA_SZ 18432
#define TW_SZ   1092                          // 1024 + 64 + 4
#define FFT_SMEM ((DATA_SZ + TW_SZ) * (int)sizeof(float2))

// Static device scratch (allocation-free rule)
__device__ float  g_h3[LL * ORD];
__device__ float  g_k [CC * LL];
__device__ float2 g_KF[CC * NFFT];            // digit-reversed spectrum / NFFT

__device__ __forceinline__ float2 cadd(float2 a, float2 b){ return make_float2(a.x+b.x, a.y+b.y); }
__device__ __forceinline__ float2 csub(float2 a, float2 b){ return make_float2(a.x-b.x, a.y-b.y); }
__device__ __forceinline__ float2 cmul(float2 a, float2 b){
    return make_float2(a.x*b.x - a.y*b.y, a.x*b.y + a.y*b.x);
}
__device__ __forceinline__ float2 cmulc(float2 a, float cr, float ci){
    return make_float2(a.x*cr - a.y*ci, a.x*ci + a.y*cr);
}
__device__ __forceinline__ float2 mni(float2 a){ return make_float2(a.y, -a.x); }   // a * -i
__device__ __forceinline__ float2 mpi(float2 a){ return make_float2(-a.y, a.x); }   // a * +i

// After dft16/idft16, output index m lives at register slot OUTI(m)
#define OUTI(m) ((((m) & 3) << 2) | ((m) >> 2))

// Twiddle tables: q=1024 @0 (w=e^{-2pi i j/16384}), q=64 @1024, q=4 @1088
__device__ __forceinline__ void fill_tw(float2* tw, int tid) {
    float sn, cs;
    if (tid < 1024) {
        sincospif((float)tid * (1.0f/8192.0f), &sn, &cs);
        tw[tid] = make_float2(cs, -sn);
    }
    if (tid < 64) {
        sincospif((float)tid * (1.0f/512.0f), &sn, &cs);
        tw[1024 + tid] = make_float2(cs, -sn);
    }
    if (tid < 4) {
        sincospif((float)tid * (1.0f/32.0f), &sn, &cs);
        tw[1088 + tid] = make_float2(cs, -sn);
    }
}

// ---- DFT16 pieces (n=4c+d, m=r+4s; X_m -> v[4r+s]) ----
__device__ __forceinline__ void dft16_tail(float2 v[16]) {
    v[5]  = cmulc(v[5],  C1f, -S1f);
    v[6]  = cmulc(v[6],  R2f, -R2f);
    v[7]  = cmulc(v[7],  S1f, -C1f);
    v[9]  = cmulc(v[9],  R2f, -R2f);
    v[10] = mni(v[10]);
    v[11] = cmulc(v[11], -R2f, -R2f);
    v[13] = cmulc(v[13], S1f, -C1f);
    v[14] = cmulc(v[14], -R2f, -R2f);
    v[15] = cmulc(v[15], -C1f, S1f);
    #pragma unroll
    for (int r = 0; r < 4; ++r) {
        float2 a = v[4*r], b = v[4*r+1], c = v[4*r+2], e = v[4*r+3];
        float2 u0 = cadd(a,c), u1 = csub(a,c), u2 = cadd(b,e), u3 = csub(b,e);
        v[4*r]   = cadd(u0,u2);
        v[4*r+1] = cadd(u1, mni(u3));
        v[4*r+2] = csub(u0,u2);
        v[4*r+3] = cadd(u1, mpi(u3));
    }
}
__device__ __forceinline__ void dft16(float2 v[16]) {
    #pragma unroll
    for (int dd = 0; dd < 4; ++dd) {
        float2 a = v[dd], b = v[4+dd], c = v[8+dd], e = v[12+dd];
        float2 t0 = cadd(a,c), t1 = csub(a,c), t2 = cadd(b,e), t3 = csub(b,e);
        v[dd]    = cadd(t0,t2);
        v[4+dd]  = cadd(t1, mni(t3));
        v[8+dd]  = csub(t0,t2);
        v[12+dd] = cadd(t1, mpi(t3));
    }
    dft16_tail(v);
}
__device__ __forceinline__ void idft16_cols_tw(float2 v[16]) {
    #pragma unroll
    for (int dd = 0; dd < 4; ++dd) {
        float2 a = v[dd], b = v[4+dd], c = v[8+dd], e = v[12+dd];
        float2 t0 = cadd(a,c), t1 = csub(a,c), t2 = cadd(b,e), t3 = csub(b,e);
        v[dd]    = cadd(t0,t2);
        v[4+dd]  = cadd(t1, mpi(t3));
        v[8+dd]  = csub(t0,t2);
        v[12+dd] = cadd(t1, mni(t3));
    }
    v[5]  = cmulc(v[5],  C1f, S1f);
    v[6]  = cmulc(v[6],  R2f, R2f);
    v[7]  = cmulc(v[7],  S1f, C1f);
    v[9]  = cmulc(v[9],  R2f, R2f);
    v[10] = mpi(v[10]);
    v[11] = cmulc(v[11], -R2f, R2f);
    v[13] = cmulc(v[13], S1f, C1f);
    v[14] = cmulc(v[14], -R2f, R2f);
    v[15] = cmulc(v[15], -C1f, -S1f);
}
__device__ __forceinline__ void idft16(float2 v[16]) {
    idft16_cols_tw(v);
    #pragma unroll
    for (int r = 0; r < 4; ++r) {
        float2 a = v[4*r], b = v[4*r+1], c = v[4*r+2], e = v[4*r+3];
        float2 u0 = cadd(a,c), u1 = csub(a,c), u2 = cadd(b,e), u3 = csub(b,e);
        v[4*r]   = cadd(u0,u2);
        v[4*r+1] = cadd(u1, mpi(u3));
        v[4*r+2] = csub(u0,u2);
        v[4*r+3] = cadd(u1, mni(u3));
    }
}

// ---- Store butterfly outputs with twiddle powers via 4 parallel chains (depth<=4) ----
__device__ __forceinline__ void store_tw16(float2* d, int base, int sh,
                                           const float2 v[16], float2 w) {
    d[SK(base)] = v[0];
    float2 W2 = cmul(w, w), W3 = cmul(W2, w), W4 = cmul(W2, W2);
    float2 a = w, b = W2, c = W3, e = W4;
    d[SK(base + (1 << sh))]  = cmul(v[OUTI(1)],  a);
    d[SK(base + (2 << sh))]  = cmul(v[OUTI(2)],  b);
    d[SK(base + (3 << sh))]  = cmul(v[OUTI(3)],  c);
    d[SK(base + (4 << sh))]  = cmul(v[OUTI(4)],  e);
    a = cmul(a, W4); b = cmul(b, W4); c = cmul(c, W4); e = cmul(e, W4);
    d[SK(base + (5 << sh))]  = cmul(v[OUTI(5)],  a);
    d[SK(base + (6 << sh))]  = cmul(v[OUTI(6)],  b);
    d[SK(base + (7 << sh))]  = cmul(v[OUTI(7)],  c);
    d[SK(base + (8 << sh))]  = cmul(v[OUTI(8)],  e);
    a = cmul(a, W4); b = cmul(b, W4); c = cmul(c, W4); e = cmul(e, W4);
    d[SK(base + (9 << sh))]  = cmul(v[OUTI(9)],  a);
    d[SK(base + (10 << sh))] = cmul(v[OUTI(10)], b);
    d[SK(base + (11 << sh))] = cmul(v[OUTI(11)], c);
    d[SK(base + (12 << sh))] = cmul(v[OUTI(12)], e);
    a = cmul(a, W4); b = cmul(b, W4); c = cmul(c, W4);
    d[SK(base + (13 << sh))] = cmul(v[OUTI(13)], a);
    d[SK(base + (14 << sh))] = cmul(v[OUTI(14)], b);
    d[SK(base + (15 << sh))] = cmul(v[OUTI(15)], c);
}

// ---- Load + multiply by conj twiddle powers (4 parallel chains) ----
__device__ __forceinline__ void load_tw16(const float2* d, int base, int sh,
                                          float2 v[16], float2 w) {
    #pragma unroll
    for (int m = 0; m < 16; ++m) v[m] = d[SK(base + (m << sh))];
    float2 W2 = cmul(w, w), W3 = cmul(W2, w), W4 = cmul(W2, W2);
    float2 a = w, b = W2, c = W3, e = W4;
    v[1]  = cmul(v[1],  a);  v[2]  = cmul(v[2],  b);
    v[3]  = cmul(v[3],  c);  v[4]  = cmul(v[4],  e);
    a = cmul(a, W4); b = cmul(b, W4); c = cmul(c, W4); e = cmul(e, W4);
    v[5]  = cmul(v[5],  a);  v[6]  = cmul(v[6],  b);
    v[7]  = cmul(v[7],  c);  v[8]  = cmul(v[8],  e);
    a = cmul(a, W4); b = cmul(b, W4); c = cmul(c, W4); e = cmul(e, W4);
    v[9]  = cmul(v[9],  a);  v[10] = cmul(v[10], b);
    v[11] = cmul(v[11], c);  v[12] = cmul(v[12], e);
    a = cmul(a, W4); b = cmul(b, W4); c = cmul(c, W4);
    v[13] = cmul(v[13], a);  v[14] = cmul(v[14], b);  v[15] = cmul(v[15], c);
}

// ---- Stage F0: radix-16, q=1024, reads two zero-padded real rows from gmem ----
__device__ __forceinline__ void f0_fwd(float2* d, const float2* tw,
                                       const float* __restrict__ r0,
                                       const float* __restrict__ r1, int tid) {
    int j = tid;
    float2 v[16];
    #pragma unroll
    for (int dd = 0; dd < 4; ++dd) {
        int ia = j + (dd << 10);
        int ib = j + ((dd + 4) << 10);
        float2 a = make_float2(r0[ia], r1[ia]);
        float2 b = make_float2(r0[ib], r1[ib]);
        v[dd]    = cadd(a, b);
        v[4+dd]  = cadd(a, mni(b));
        v[8+dd]  = csub(a, b);
        v[12+dd] = cadd(a, mpi(b));
    }
    dft16_tail(v);
    store_tw16(d, j, 10, v, tw[j]);
    __syncthreads();
}

// ---- Middle radix-16 stages ----
__device__ __forceinline__ void r16_fwd(float2* d, const float2* tw, int logq, int off, int tid) {
    int q = 1 << logq;
    int j = tid & (q - 1);
    int base = ((tid >> logq) << (logq + 4)) | j;
    float2 v[16];
    #pragma unroll
    for (int m = 0; m < 16; ++m) v[m] = d[SK(base + (m << logq))];
    dft16(v);
    store_tw16(d, base, logq, v, tw[off + j]);
    __syncthreads();
}
__device__ __forceinline__ void r16_inv(float2* d, const float2* tw, int logq, int off, int tid) {
    int q = 1 << logq;
    int j = tid & (q - 1);
    int base = ((tid >> logq) << (logq + 4)) | j;
    float2 w = tw[off + j]; w.y = -w.y;
    float2 v[16];
    load_tw16(d, base, logq, v, w);
    idft16(v);
    #pragma unroll
    for (int m = 0; m < 16; ++m) d[SK(base + (m << logq))] = v[OUTI(m)];
    __syncthreads();
}

// ---- Stage F3: final forward radix-4 (q=1), standalone (kf kernel) ----
__device__ __forceinline__ void f3_fwd(float2* d, int tid) {
    int base = tid << 4;
    float4* p4 = (float4*)(d + SK(base));
    float2 v[16];
    #pragma unroll
    for (int u = 0; u < 8; ++u) {
        float4 t = p4[u];
        v[2*u]   = make_float2(t.x, t.y);
        v[2*u+1] = make_float2(t.z, t.w);
    }
    #pragma unroll
    for (int k = 0; k < 4; ++k) {
        float2 a0 = v[4*k], a1 = v[4*k+1], a2 = v[4*k+2], a3 = v[4*k+3];
        float2 t0 = cadd(a0,a2), t1 = csub(a0,a2), t2 = cadd(a1,a3), t3 = csub(a1,a3);
        v[4*k]   = cadd(t0,t2);
        v[4*k+1] = cadd(t1, mni(t3));
        v[4*k+2] = csub(t0,t2);
        v[4*k+3] = cadd(t1, mpi(t3));
    }
    #pragma unroll
    for (int u = 0; u < 8; ++u)
        p4[u] = make_float4(v[2*u].x, v[2*u].y, v[2*u+1].x, v[2*u+1].y);
    __syncthreads();
}

// ---- Fused stage: fwd radix-4 (q=1) + pointwise Kf + inv radix-4 (q=1), in registers ----
__device__ __forceinline__ void f3i0_fused(float2* d, const float2* __restrict__ kf, int tid) {
    int base = tid << 4;
    float4* p4 = (float4*)(d + SK(base));
    const float4* k4 = (const float4*)(kf + base);
    float2 v[16];
    #pragma unroll
    for (int u = 0; u < 8; ++u) {
        float4 t = p4[u];
        v[2*u]   = make_float2(t.x, t.y);
        v[2*u+1] = make_float2(t.z, t.w);
    }
    #pragma unroll
    for (int k = 0; k < 4; ++k) {
        float2 a0 = v[4*k], a1 = v[4*k+1], a2 = v[4*k+2], a3 = v[4*k+3];
        float2 t0 = cadd(a0,a2), t1 = csub(a0,a2), t2 = cadd(a1,a3), t3 = csub(a1,a3);
        v[4*k]   = cadd(t0,t2);
        v[4*k+1] = cadd(t1, mni(t3));
        v[4*k+2] = csub(t0,t2);
        v[4*k+3] = cadd(t1, mpi(t3));
    }
    #pragma unroll
    for (int u = 0; u < 8; ++u) {
        float4 kk = k4[u];
        v[2*u]   = cmul(v[2*u],   make_float2(kk.x, kk.y));
        v[2*u+1] = cmul(v[2*u+1], make_float2(kk.z, kk.w));
    }
    #pragma unroll
    for (int k = 0; k < 4; ++k) {
        float2 a0 = v[4*k], a1 = v[4*k+1], a2 = v[4*k+2], a3 = v[4*k+3];
        float2 t0 = cadd(a0,a2), t1 = csub(a0,a2), t2 = cadd(a1,a3), t3 = csub(a1,a3);
        v[4*k]   = cadd(t0,t2);
        v[4*k+1] = cadd(t1, mpi(t3));
        v[4*k+2] = csub(t0,t2);
        v[4*k+3] = cadd(t1, mni(t3));
    }
    #pragma unroll
    for (int u = 0; u < 8; ++u)
        p4[u] = make_float4(v[2*u].x, v[2*u].y, v[2*u+1].x, v[2*u+1].y);
    __syncthreads();
}

// ---- Stage I3: inverse radix-16 q=1024, only outputs m<8, write gmem + bias ----
__device__ __forceinline__ void i3_store(const float2* d, const float2* tw,
                                         const float* __restrict__ x0,
                                         const float* __restrict__ x1,
                                         float* __restrict__ o0,
                                         float* __restrict__ o1,
                                         float bc, int tid) {
    int j = tid;
    float2 w = tw[j]; w.y = -w.y;
    float2 v[16];
    load_tw16(d, j, 10, v, w);
    idft16_cols_tw(v);
    #pragma unroll
    for (int r = 0; r < 4; ++r) {
        float2 a = v[4*r], b = v[4*r+1], c = v[4*r+2], e = v[4*r+3];
        float2 u0 = cadd(a,c), u1 = csub(a,c), u2 = cadd(b,e), u3 = csub(b,e);
        float2 y0 = cadd(u0,u2);
        float2 y1 = cadd(u1, mpi(u3));
        int i0 = j + (r << 10);
        int i1 = j + ((r + 4) << 10);
        o0[i0] = y0.x + x0[i0] * bc;  o1[i0] = y0.y + x1[i0] * bc;
        o0[i1] = y1.x + x0[i1] * bc;  o1[i1] = y1.y + x1[i1] * bc;
    }
}

// ---------------- Kernel 1: implicit MLP, 4 positions in parallel per block -------
__global__ void mlp_hidden_kernel(const float* __restrict__ z,
                                  const float* __restrict__ W0, const float* __restrict__ b0,
                                  const float* __restrict__ W1, const float* __restrict__ b1,
                                  const float* __restrict__ W2, const float* __restrict__ b2,
                                  const float* __restrict__ freq) {
    __shared__ float sW0[EMB * ORD];
    __shared__ float sW1[ORD * ORD];
    __shared__ float sW2[ORD * ORD];
    __shared__ float sz [4][36];
    __shared__ float sh1[4][65];
    __shared__ float sh2[4][65];

    int tid = threadIdx.x;
    int o = tid & 63;
    int p = tid >> 6;
    for (int i = tid; i < EMB * ORD; i += 256) sW0[i] = W0[i];
    for (int i = tid; i < ORD * ORD; i += 256) sW1[i] = W1[i];
    for (int i = tid; i < ORD * ORD; i += 256) sW2[i] = W2[i];
    float fb0 = b0[o], fb1 = b1[o], fb2 = b2[o], fq = freq[o];

    int l = blockIdx.x * 4 + p;
    if (o < EMB) sz[p][o] = z[l * EMB + o];
    __syncthreads();

    float acc = fb0;
    #pragma unroll
    for (int e = 0; e < EMB; ++e) acc += sz[p][e] * sW0[e * ORD + o];
    sh1[p][o] = sinf(fq * acc);
    __syncthreads();
    acc = fb1;
    #pragma unroll 8
    for (int i = 0; i < ORD; ++i) acc += sh1[p][i] * sW1[i * ORD + o];
    sh2[p][o] = sinf(fq * acc);
    __syncthreads();
    acc = fb2;
    #pragma unroll 8
    for (int i = 0; i < ORD; ++i) acc += sh2[p][i] * sW2[i * ORD + o];
    g_h3[l * ORD + o] = sinf(fq * acc);
}

// ---------------- Kernel 2: output projection + exponential modulation ------------
__global__ void proj_kernel(const float* __restrict__ Wout,
                            const float* __restrict__ deltas) {
    __shared__ float4 sH4[32 * 17];
    __shared__ float4 sW4[64 * 32];
    float* sH = (float*)sH4;
    float* sW = (float*)sW4;

    int tid = threadIdx.x;
    int lt  = blockIdx.x * 32;
    int cb  = blockIdx.y * 384;

    for (int idx = tid; idx < 32 * ORD; idx += 256) {
        int l_ = idx >> 6, o = idx & 63;
        sH[l_ * 68 + o] = g_h3[(lt + l_) * ORD + o];
    }
    __syncthreads();

    int ll = tid & 31;
    int cq = tid >> 5;
    float hreg[ORD];
    {
        const float4* row = (const float4*)(sH + ll * 68);
        #pragma unroll
        for (int i = 0; i < 16; ++i) {
            float4 t = row[i];
            hreg[4*i] = t.x; hreg[4*i+1] = t.y; hreg[4*i+2] = t.z; hreg[4*i+3] = t.w;
        }
    }
    float tl = (float)(lt + ll) * (1.0f / (float)(LL - 1));

    for (int ch = 0; ch < 3; ++ch) {
        int c0 = cb + ch * 128;
        __syncthreads();
        for (int idx = tid; idx < ORD * 128; idx += 256) {
            int o = idx >> 7, cc = idx & 127;
            sW[o * 128 + cc] = Wout[o * CC + c0 + cc];
        }
        __syncthreads();

        float acc[16];
        #pragma unroll
        for (int j = 0; j < 16; ++j) acc[j] = 0.0f;
        #pragma unroll 8
        for (int o = 0; o < ORD; ++o) {
            float h = hreg[o];
            const float4* row = sW4 + o * 32 + cq * 4;
            #pragma unroll
            for (int j = 0; j < 4; ++j) {
                float4 w = row[j];
                acc[4*j+0] += h * w.x;
                acc[4*j+1] += h * w.y;
                acc[4*j+2] += h * w.z;
                acc[4*j+3] += h * w.w;
            }
        }
        #pragma unroll
        for (int j = 0; j < 16; ++j) {
            int c = c0 + cq * 16 + j;
            float m = expf(-tl * fabsf(deltas[c]));
            g_k[c * LL + lt + ll] = acc[j] * m;
        }
    }
}

// ---------------- Kernel 3: filter spectra, two channels per FFT ------------------
__global__ void __launch_bounds__(NT, 1) kf_fft_kernel() {
    extern __shared__ float2 sm[];
    float2* data = sm;
    float2* tw   = sm + DATA_SZ;
    int tid = threadIdx.x;
    int c0  = blockIdx.x * 2;
    int c1  = c0 + 1;

    fill_tw(tw, tid);
    f0_fwd(data, tw, g_k + (size_t)c0 * LL, g_k + (size_t)c1 * LL, tid);
    r16_fwd(data, tw, 6, 1024, tid);
    r16_fwd(data, tw, 2, 1088, tid);
    f3_fwd(data, tid);

    const float s = 0.5f / (float)NFFT;
    float2* KF0 = g_KF + (size_t)c0 * NFFT;
    float2* KF1 = g_KF + (size_t)c1 * NFFT;
    for (int p = tid; p < NFFT; p += NT) {
        int j  = (p >> 10) | (((p >> 6) & 15) << 4) | (((p >> 2) & 15) << 8) | ((p & 3) << 12);
        int jn = (NFFT - j) & (NFFT - 1);
        int pp = ((jn & 15) << 10) | (((jn >> 4) & 15) << 6) | (((jn >> 8) & 15) << 2) | (jn >> 12);
        float2 z1 = data[SK(p)];
        float2 z2 = data[SK(pp)];
        KF0[p] = make_float2(s * (z1.x + z2.x), s * (z1.y - z2.y));
        KF1[p] = make_float2(s * (z1.y + z2.y), s * (z2.x - z1.x));
    }
}

// ---------------- Kernel 4: batched FFT convolution (2 batches as one complex) ----
__global__ void __launch_bounds__(NT, 1) conv_fft_kernel(const float* __restrict__ x,
                                                         const float* __restrict__ bias,
                                                         float* __restrict__ out) {
    extern __shared__ float2 sm[];
    float2* data = sm;
    float2* tw   = sm + DATA_SZ;
    int tid = threadIdx.x;
    int c = blockIdx.x;
    int p = blockIdx.y;

    const float* x0 = x + ((size_t)(2*p)   * CC + c) * LL;
    const float* x1 = x + ((size_t)(2*p+1) * CC + c) * LL;

    fill_tw(tw, tid);
    f0_fwd(data, tw, x0, x1, tid);
    r16_fwd(data, tw, 6, 1024, tid);
    r16_fwd(data, tw, 2, 1088, tid);

    f3i0_fused(data, g_KF + (size_t)c * NFFT, tid);

    r16_inv(data, tw, 2, 1088, tid);
    r16_inv(data, tw, 6, 1024, tid);

    float bc = bias[c];
    float* o0 = out + ((size_t)(2*p)   * CC + c) * LL;
    float* o1 = out + ((size_t)(2*p+1) * CC + c) * LL;
    i3_store(data, tw, x0, x1, o0, o1, bc, tid);
}

extern "C" void kernel_launch(void* const* d_in, const int* in_sizes, int n_in,
                              void* d_out, int out_size) {
    const float* x      = (const float*)d_in[0];
    const float* bias   = (const float*)d_in[1];
    const float* z      = (const float*)d_in[2];
    const float* deltas = (const float*)d_in[3];
    const float* W0     = (const float*)d_in[4];
    const float* b0     = (const float*)d_in[5];
    const float* W1     = (const float*)d_in[6];
    const float* b1     = (const float*)d_in[7];
    const float* W2     = (const float*)d_in[8];
    const float* b2     = (const float*)d_in[9];
    const float* freq   = (const float*)d_in[10];
    const float* Wout   = (const float*)d_in[11];
    float* out = (float*)d_out;

    cudaFuncSetAttribute(kf_fft_kernel,   cudaFuncAttributeMaxDynamicSharedMemorySize, FFT_SMEM);
    cudaFuncSetAttribute(conv_fft_kernel, cudaFuncAttributeMaxDynamicSharedMemorySize, FFT_SMEM);

    mlp_hidden_kernel<<<LL / 4, 256>>>(z, W0, b0, W1, b1, W2, b2, freq);
    proj_kernel<<<dim3(LL / 32, 2), 256>>>(Wout, deltas);
    kf_fft_kernel<<<CC / 2, NT, FFT_SMEM>>>();
    conv_fft_kernel<<<dim3(CC, BB / 2), NT, FFT_SMEM>>>(x, bias, out);
}

// round 7
// speedup vs baseline: 2.8941x; 1.0472x over previous
#include <cuda_runtime.h>
#include <math.h>

// Problem constants
#define BB    4
#define CC    768
#define LL    8192
#define NFFT  16384
#define EMB   33
#define ORD   64
#define NT    1024

#define C1f 0.923879532511287f   // cos(pi/8)
#define S1f 0.382683432365090f   // sin(pi/8)
#define R2f 0.707106781186548f   // sqrt(2)/2

// Skewed shared index: groups of 16 float2 stay contiguous & 16B-aligned
#define SK(i) ((i) + (((i) >> 4) << 1))
#define DATA_SZ 18432
#define TW_SZ   1092                          // 1024 + 64 + 4
#define FFT_SMEM ((DATA_SZ + TW_SZ) * (int)sizeof(float2))

// Static device scratch (allocation-free rule)
__device__ float  g_h3[LL * ORD];
__device__ float  g_k [CC * LL];
__device__ float2 g_KF[CC * NFFT];            // digit-reversed spectrum / NFFT

__device__ __forceinline__ float2 cadd(float2 a, float2 b){ return make_float2(a.x+b.x, a.y+b.y); }
__device__ __forceinline__ float2 csub(float2 a, float2 b){ return make_float2(a.x-b.x, a.y-b.y); }
__device__ __forceinline__ float2 cmul(float2 a, float2 b){
    return make_float2(a.x*b.x - a.y*b.y, a.x*b.y + a.y*b.x);
}
__device__ __forceinline__ float2 cmulc(float2 a, float cr, float ci){
    return make_float2(a.x*cr - a.y*ci, a.x*ci + a.y*cr);
}
__device__ __forceinline__ float2 mni(float2 a){ return make_float2(a.y, -a.x); }   // a * -i
__device__ __forceinline__ float2 mpi(float2 a){ return make_float2(-a.y, a.x); }   // a * +i

// 128-thread named barrier; ids 1..8 (id 0 reserved for __syncthreads).
// The q=64<->q=4 exchange group is tid>>6 (64 threads), strictly contained
// in the 128-thread group tid>>7.
__device__ __forceinline__ void bar128(int tid){
    asm volatile("bar.sync %0, 128;" :: "r"(1 + (tid >> 7)) : "memory");
}

// After dft16/idft16, output index m lives at register slot OUTI(m)
#define OUTI(m) ((((m) & 3) << 2) | ((m) >> 2))

// Twiddle tables: q=1024 @0 (w=e^{-2pi i j/16384}), q=64 @1024, q=4 @1088
__device__ __forceinline__ void fill_tw(float2* tw, int tid) {
    float sn, cs;
    if (tid < 1024) {
        sincospif((float)tid * (1.0f/8192.0f), &sn, &cs);
        tw[tid] = make_float2(cs, -sn);
    }
    if (tid < 64) {
        sincospif((float)tid * (1.0f/512.0f), &sn, &cs);
        tw[1024 + tid] = make_float2(cs, -sn);
    }
    if (tid < 4) {
        sincospif((float)tid * (1.0f/32.0f), &sn, &cs);
        tw[1088 + tid] = make_float2(cs, -sn);
    }
}

// ---- DFT16 pieces (n=4c+d, m=r+4s; X_m -> v[4r+s]) ----
__device__ __forceinline__ void dft16_tail(float2 v[16]) {
    v[5]  = cmulc(v[5],  C1f, -S1f);
    v[6]  = cmulc(v[6],  R2f, -R2f);
    v[7]  = cmulc(v[7],  S1f, -C1f);
    v[9]  = cmulc(v[9],  R2f, -R2f);
    v[10] = mni(v[10]);
    v[11] = cmulc(v[11], -R2f, -R2f);
    v[13] = cmulc(v[13], S1f, -C1f);
    v[14] = cmulc(v[14], -R2f, -R2f);
    v[15] = cmulc(v[15], -C1f, S1f);
    #pragma unroll
    for (int r = 0; r < 4; ++r) {
        float2 a = v[4*r], b = v[4*r+1], c = v[4*r+2], e = v[4*r+3];
        float2 u0 = cadd(a,c), u1 = csub(a,c), u2 = cadd(b,e), u3 = csub(b,e);
        v[4*r]   = cadd(u0,u2);
        v[4*r+1] = cadd(u1, mni(u3));
        v[4*r+2] = csub(u0,u2);
        v[4*r+3] = cadd(u1, mpi(u3));
    }
}
__device__ __forceinline__ void dft16(float2 v[16]) {
    #pragma unroll
    for (int dd = 0; dd < 4; ++dd) {
        float2 a = v[dd], b = v[4+dd], c = v[8+dd], e = v[12+dd];
        float2 t0 = cadd(a,c), t1 = csub(a,c), t2 = cadd(b,e), t3 = csub(b,e);
        v[dd]    = cadd(t0,t2);
        v[4+dd]  = cadd(t1, mni(t3));
        v[8+dd]  = csub(t0,t2);
        v[12+dd] = cadd(t1, mpi(t3));
    }
    dft16_tail(v);
}
__device__ __forceinline__ void idft16_cols_tw(float2 v[16]) {
    #pragma unroll
    for (int dd = 0; dd < 4; ++dd) {
        float2 a = v[dd], b = v[4+dd], c = v[8+dd], e = v[12+dd];
        float2 t0 = cadd(a,c), t1 = csub(a,c), t2 = cadd(b,e), t3 = csub(b,e);
        v[dd]    = cadd(t0,t2);
        v[4+dd]  = cadd(t1, mpi(t3));
        v[8+dd]  = csub(t0,t2);
        v[12+dd] = cadd(t1, mni(t3));
    }
    v[5]  = cmulc(v[5],  C1f, S1f);
    v[6]  = cmulc(v[6],  R2f, R2f);
    v[7]  = cmulc(v[7],  S1f, C1f);
    v[9]  = cmulc(v[9],  R2f, R2f);
    v[10] = mpi(v[10]);
    v[11] = cmulc(v[11], -R2f, R2f);
    v[13] = cmulc(v[13], S1f, C1f);
    v[14] = cmulc(v[14], -R2f, R2f);
    v[15] = cmulc(v[15], -C1f, -S1f);
}
__device__ __forceinline__ void idft16(float2 v[16]) {
    idft16_cols_tw(v);
    #pragma unroll
    for (int r = 0; r < 4; ++r) {
        float2 a = v[4*r], b = v[4*r+1], c = v[4*r+2], e = v[4*r+3];
        float2 u0 = cadd(a,c), u1 = csub(a,c), u2 = cadd(b,e), u3 = csub(b,e);
        v[4*r]   = cadd(u0,u2);
        v[4*r+1] = cadd(u1, mpi(u3));
        v[4*r+2] = csub(u0,u2);
        v[4*r+3] = cadd(u1, mni(u3));
    }
}

// ---- Store butterfly outputs with twiddle powers via 4 parallel chains (depth<=4) ----
__device__ __forceinline__ void store_tw16(float2* d, int base, int sh,
                                           const float2 v[16], float2 w) {
    d[SK(base)] = v[0];
    float2 W2 = cmul(w, w), W3 = cmul(W2, w), W4 = cmul(W2, W2);
    float2 a = w, b = W2, c = W3, e = W4;
    d[SK(base + (1 << sh))]  = cmul(v[OUTI(1)],  a);
    d[SK(base + (2 << sh))]  = cmul(v[OUTI(2)],  b);
    d[SK(base + (3 << sh))]  = cmul(v[OUTI(3)],  c);
    d[SK(base + (4 << sh))]  = cmul(v[OUTI(4)],  e);
    a = cmul(a, W4); b = cmul(b, W4); c = cmul(c, W4); e = cmul(e, W4);
    d[SK(base + (5 << sh))]  = cmul(v[OUTI(5)],  a);
    d[SK(base + (6 << sh))]  = cmul(v[OUTI(6)],  b);
    d[SK(base + (7 << sh))]  = cmul(v[OUTI(7)],  c);
    d[SK(base + (8 << sh))]  = cmul(v[OUTI(8)],  e);
    a = cmul(a, W4); b = cmul(b, W4); c = cmul(c, W4); e = cmul(e, W4);
    d[SK(base + (9 << sh))]  = cmul(v[OUTI(9)],  a);
    d[SK(base + (10 << sh))] = cmul(v[OUTI(10)], b);
    d[SK(base + (11 << sh))] = cmul(v[OUTI(11)], c);
    d[SK(base + (12 << sh))] = cmul(v[OUTI(12)], e);
    a = cmul(a, W4); b = cmul(b, W4); c = cmul(c, W4);
    d[SK(base + (13 << sh))] = cmul(v[OUTI(13)], a);
    d[SK(base + (14 << sh))] = cmul(v[OUTI(14)], b);
    d[SK(base + (15 << sh))] = cmul(v[OUTI(15)], c);
}

// ---- Load + multiply by conj twiddle powers (4 parallel chains) ----
__device__ __forceinline__ void load_tw16(const float2* d, int base, int sh,
                                          float2 v[16], float2 w) {
    #pragma unroll
    for (int m = 0; m < 16; ++m) v[m] = d[SK(base + (m << sh))];
    float2 W2 = cmul(w, w), W3 = cmul(W2, w), W4 = cmul(W2, W2);
    float2 a = w, b = W2, c = W3, e = W4;
    v[1]  = cmul(v[1],  a);  v[2]  = cmul(v[2],  b);
    v[3]  = cmul(v[3],  c);  v[4]  = cmul(v[4],  e);
    a = cmul(a, W4); b = cmul(b, W4); c = cmul(c, W4); e = cmul(e, W4);
    v[5]  = cmul(v[5],  a);  v[6]  = cmul(v[6],  b);
    v[7]  = cmul(v[7],  c);  v[8]  = cmul(v[8],  e);
    a = cmul(a, W4); b = cmul(b, W4); c = cmul(c, W4); e = cmul(e, W4);
    v[9]  = cmul(v[9],  a);  v[10] = cmul(v[10], b);
    v[11] = cmul(v[11], c);  v[12] = cmul(v[12], e);
    a = cmul(a, W4); b = cmul(b, W4); c = cmul(c, W4);
    v[13] = cmul(v[13], a);  v[14] = cmul(v[14], b);  v[15] = cmul(v[15], c);
}

// ---- Stage F0: radix-16, q=1024, reads two zero-padded real rows from gmem ----
// Ends with a block-wide barrier (next stage reads across all threads).
__device__ __forceinline__ void f0_fwd(float2* d, const float2* tw,
                                       const float* __restrict__ r0,
                                       const float* __restrict__ r1, int tid) {
    int j = tid;
    float2 v[16];
    #pragma unroll
    for (int dd = 0; dd < 4; ++dd) {
        int ia = j + (dd << 10);
        int ib = j + ((dd + 4) << 10);
        float2 a = make_float2(r0[ia], r1[ia]);
        float2 b = make_float2(r0[ib], r1[ib]);
        v[dd]    = cadd(a, b);
        v[4+dd]  = cadd(a, mni(b));
        v[8+dd]  = csub(a, b);
        v[12+dd] = cadd(a, mpi(b));
    }
    dft16_tail(v);
    store_tw16(d, j, 10, v, tw[j]);
    __syncthreads();
}

// ---- Middle radix-16 stages (no trailing barrier; caller chooses scope) ----
__device__ __forceinline__ void r16_fwd(float2* d, const float2* tw, int logq, int off, int tid) {
    int q = 1 << logq;
    int j = tid & (q - 1);
    int base = ((tid >> logq) << (logq + 4)) | j;
    float2 v[16];
    #pragma unroll
    for (int m = 0; m < 16; ++m) v[m] = d[SK(base + (m << logq))];
    dft16(v);
    store_tw16(d, base, logq, v, tw[off + j]);
}
__device__ __forceinline__ void r16_inv(float2* d, const float2* tw, int logq, int off, int tid) {
    int q = 1 << logq;
    int j = tid & (q - 1);
    int base = ((tid >> logq) << (logq + 4)) | j;
    float2 w = tw[off + j]; w.y = -w.y;
    float2 v[16];
    load_tw16(d, base, logq, v, w);
    idft16(v);
    #pragma unroll
    for (int m = 0; m < 16; ++m) d[SK(base + (m << logq))] = v[OUTI(m)];
}

// ---- Stage F3: final forward radix-4 (q=1), standalone (kf kernel) ----
__device__ __forceinline__ void f3_fwd(float2* d, int tid) {
    int base = tid << 4;
    float4* p4 = (float4*)(d + SK(base));
    float2 v[16];
    #pragma unroll
    for (int u = 0; u < 8; ++u) {
        float4 t = p4[u];
        v[2*u]   = make_float2(t.x, t.y);
        v[2*u+1] = make_float2(t.z, t.w);
    }
    #pragma unroll
    for (int k = 0; k < 4; ++k) {
        float2 a0 = v[4*k], a1 = v[4*k+1], a2 = v[4*k+2], a3 = v[4*k+3];
        float2 t0 = cadd(a0,a2), t1 = csub(a0,a2), t2 = cadd(a1,a3), t3 = csub(a1,a3);
        v[4*k]   = cadd(t0,t2);
        v[4*k+1] = cadd(t1, mni(t3));
        v[4*k+2] = csub(t0,t2);
        v[4*k+3] = cadd(t1, mpi(t3));
    }
    #pragma unroll
    for (int u = 0; u < 8; ++u)
        p4[u] = make_float4(v[2*u].x, v[2*u].y, v[2*u+1].x, v[2*u+1].y);
    __syncthreads();
}

// ---- Fused stage: fwd radix-4 (q=1) + pointwise Kf + inv radix-4 (q=1), in registers ----
__device__ __forceinline__ void f3i0_fused(float2* d, const float2* __restrict__ kf, int tid) {
    int base = tid << 4;
    float4* p4 = (float4*)(d + SK(base));
    const float4* k4 = (const float4*)(kf + base);
    float2 v[16];
    #pragma unroll
    for (int u = 0; u < 8; ++u) {
        float4 t = p4[u];
        v[2*u]   = make_float2(t.x, t.y);
        v[2*u+1] = make_float2(t.z, t.w);
    }
    #pragma unroll
    for (int k = 0; k < 4; ++k) {
        float2 a0 = v[4*k], a1 = v[4*k+1], a2 = v[4*k+2], a3 = v[4*k+3];
        float2 t0 = cadd(a0,a2), t1 = csub(a0,a2), t2 = cadd(a1,a3), t3 = csub(a1,a3);
        v[4*k]   = cadd(t0,t2);
        v[4*k+1] = cadd(t1, mni(t3));
        v[4*k+2] = csub(t0,t2);
        v[4*k+3] = cadd(t1, mpi(t3));
    }
    #pragma unroll
    for (int u = 0; u < 8; ++u) {
        float4 kk = k4[u];
        v[2*u]   = cmul(v[2*u],   make_float2(kk.x, kk.y));
        v[2*u+1] = cmul(v[2*u+1], make_float2(kk.z, kk.w));
    }
    #pragma unroll
    for (int k = 0; k < 4; ++k) {
        float2 a0 = v[4*k], a1 = v[4*k+1], a2 = v[4*k+2], a3 = v[4*k+3];
        float2 t0 = cadd(a0,a2), t1 = csub(a0,a2), t2 = cadd(a1,a3), t3 = csub(a1,a3);
        v[4*k]   = cadd(t0,t2);
        v[4*k+1] = cadd(t1, mpi(t3));
        v[4*k+2] = csub(t0,t2);
        v[4*k+3] = cadd(t1, mni(t3));
    }
    #pragma unroll
    for (int u = 0; u < 8; ++u)
        p4[u] = make_float4(v[2*u].x, v[2*u].y, v[2*u+1].x, v[2*u+1].y);
}

// ---- Stage I3: inverse radix-16 q=1024, only outputs m<8, write gmem + bias ----
__device__ __forceinline__ void i3_store(const float2* d, const float2* tw,
                                         const float* __restrict__ x0,
                                         const float* __restrict__ x1,
                                         float* __restrict__ o0,
                                         float* __restrict__ o1,
                                         float bc, int tid) {
    int j = tid;
    float2 w = tw[j]; w.y = -w.y;
    float2 v[16];
    load_tw16(d, j, 10, v, w);
    idft16_cols_tw(v);
    #pragma unroll
    for (int r = 0; r < 4; ++r) {
        float2 a = v[4*r], b = v[4*r+1], c = v[4*r+2], e = v[4*r+3];
        float2 u0 = cadd(a,c), u1 = csub(a,c), u2 = cadd(b,e), u3 = csub(b,e);
        float2 y0 = cadd(u0,u2);
        float2 y1 = cadd(u1, mpi(u3));
        int i0 = j + (r << 10);
        int i1 = j + ((r + 4) << 10);
        o0[i0] = y0.x + x0[i0] * bc;  o1[i0] = y0.y + x1[i0] * bc;
        o0[i1] = y1.x + x0[i1] * bc;  o1[i1] = y1.y + x1[i1] * bc;
    }
}

// ---------------- Kernel 1: implicit MLP, 32 positions per block -------------------
__global__ void mlp_hidden_kernel(const float* __restrict__ z,
                                  const float* __restrict__ W0, const float* __restrict__ b0,
                                  const float* __restrict__ W1, const float* __restrict__ b1,
                                  const float* __restrict__ W2, const float* __restrict__ b2,
                                  const float* __restrict__ freq) {
    __shared__ float sW0[EMB * ORD];
    __shared__ float sW1[ORD * ORD];
    __shared__ float sW2[ORD * ORD];
    __shared__ float sz [4][36];
    __shared__ float sh1[4][65];
    __shared__ float sh2[4][65];

    int tid = threadIdx.x;
    int o = tid & 63;
    int p = tid >> 6;
    for (int i = tid; i < EMB * ORD; i += 256) sW0[i] = W0[i];
    for (int i = tid; i < ORD * ORD; i += 256) sW1[i] = W1[i];
    for (int i = tid; i < ORD * ORD; i += 256) sW2[i] = W2[i];
    float fb0 = b0[o], fb1 = b1[o], fb2 = b2[o], fq = freq[o];
    __syncthreads();

    int l0 = blockIdx.x * 32;
    for (int it = 0; it < 8; ++it) {
        int l = l0 + it * 4 + p;
        if (o < EMB) sz[p][o] = z[l * EMB + o];
        __syncthreads();
        float acc = fb0;
        #pragma unroll
        for (int e = 0; e < EMB; ++e) acc += sz[p][e] * sW0[e * ORD + o];
        sh1[p][o] = sinf(fq * acc);
        __syncthreads();
        acc = fb1;
        #pragma unroll 8
        for (int i = 0; i < ORD; ++i) acc += sh1[p][i] * sW1[i * ORD + o];
        sh2[p][o] = sinf(fq * acc);
        __syncthreads();
        acc = fb2;
        #pragma unroll 8
        for (int i = 0; i < ORD; ++i) acc += sh2[p][i] * sW2[i * ORD + o];
        g_h3[l * ORD + o] = sinf(fq * acc);
        __syncthreads();
    }
}

// ---------------- Kernel 2: output projection + exponential modulation ------------
__global__ void proj_kernel(const float* __restrict__ Wout,
                            const float* __restrict__ deltas) {
    __shared__ float4 sH4[32 * 17];
    __shared__ float4 sW4[64 * 32];
    float* sH = (float*)sH4;
    float* sW = (float*)sW4;

    int tid = threadIdx.x;
    int lt  = blockIdx.x * 32;
    int cb  = blockIdx.y * 384;

    for (int idx = tid; idx < 32 * ORD; idx += 256) {
        int l_ = idx >> 6, o = idx & 63;
        sH[l_ * 68 + o] = g_h3[(lt + l_) * ORD + o];
    }
    __syncthreads();

    int ll = tid & 31;
    int cq = tid >> 5;
    float hreg[ORD];
    {
        const float4* row = (const float4*)(sH + ll * 68);
        #pragma unroll
        for (int i = 0; i < 16; ++i) {
            float4 t = row[i];
            hreg[4*i] = t.x; hreg[4*i+1] = t.y; hreg[4*i+2] = t.z; hreg[4*i+3] = t.w;
        }
    }
    float tl = (float)(lt + ll) * (1.0f / (float)(LL - 1));

    for (int ch = 0; ch < 3; ++ch) {
        int c0 = cb + ch * 128;
        __syncthreads();
        for (int idx = tid; idx < ORD * 128; idx += 256) {
            int o = idx >> 7, cc = idx & 127;
            sW[o * 128 + cc] = Wout[o * CC + c0 + cc];
        }
        __syncthreads();

        float acc[16];
        #pragma unroll
        for (int j = 0; j < 16; ++j) acc[j] = 0.0f;
        #pragma unroll 8
        for (int o = 0; o < ORD; ++o) {
            float h = hreg[o];
            const float4* row = sW4 + o * 32 + cq * 4;
            #pragma unroll
            for (int j = 0; j < 4; ++j) {
                float4 w = row[j];
                acc[4*j+0] += h * w.x;
                acc[4*j+1] += h * w.y;
                acc[4*j+2] += h * w.z;
                acc[4*j+3] += h * w.w;
            }
        }
        #pragma unroll
        for (int j = 0; j < 16; ++j) {
            int c = c0 + cq * 16 + j;
            float m = expf(-tl * fabsf(deltas[c]));
            g_k[c * LL + lt + ll] = acc[j] * m;
        }
    }
}

// ---------------- Kernel 3: filter spectra, two channels per FFT ------------------
__global__ void __launch_bounds__(NT, 1) kf_fft_kernel() {
    extern __shared__ float2 sm[];
    float2* data = sm;
    float2* tw   = sm + DATA_SZ;
    int tid = threadIdx.x;
    int c0  = blockIdx.x * 2;
    int c1  = c0 + 1;

    fill_tw(tw, tid);
    f0_fwd(data, tw, g_k + (size_t)c0 * LL, g_k + (size_t)c1 * LL, tid);
    r16_fwd(data, tw, 6, 1024, tid);
    bar128(tid);
    r16_fwd(data, tw, 2, 1088, tid);
    __syncwarp();
    f3_fwd(data, tid);   // ends with __syncthreads (split loop reads globally)

    const float s = 0.5f / (float)NFFT;
    float2* KF0 = g_KF + (size_t)c0 * NFFT;
    float2* KF1 = g_KF + (size_t)c1 * NFFT;
    for (int p = tid; p < NFFT; p += NT) {
        int j  = (p >> 10) | (((p >> 6) & 15) << 4) | (((p >> 2) & 15) << 8) | ((p & 3) << 12);
        int jn = (NFFT - j) & (NFFT - 1);
        int pp = ((jn & 15) << 10) | (((jn >> 4) & 15) << 6) | (((jn >> 8) & 15) << 2) | (jn >> 12);
        float2 z1 = data[SK(p)];
        float2 z2 = data[SK(pp)];
        KF0[p] = make_float2(s * (z1.x + z2.x), s * (z1.y - z2.y));
        KF1[p] = make_float2(s * (z1.y + z2.y), s * (z2.x - z1.x));
    }
}

// ---------------- Kernel 4: batched FFT convolution (2 batches as one complex) ----
__global__ void __launch_bounds__(NT, 1) conv_fft_kernel(const float* __restrict__ x,
                                                         const float* __restrict__ bias,
                                                         float* __restrict__ out) {
    extern __shared__ float2 sm[];
    float2* data = sm;
    float2* tw   = sm + DATA_SZ;
    int tid = threadIdx.x;
    int c = blockIdx.x;
    int p = blockIdx.y;

    const float* x0 = x + ((size_t)(2*p)   * CC + c) * LL;
    const float* x1 = x + ((size_t)(2*p+1) * CC + c) * LL;

    fill_tw(tw, tid);
    f0_fwd(data, tw, x0, x1, tid);          // block barrier inside

    r16_fwd(data, tw, 6, 1024, tid);
    bar128(tid);                            // exchange stays within tid>>6 group
    r16_fwd(data, tw, 2, 1088, tid);
    __syncwarp();                           // exchange within aligned 4-thread group

    f3i0_fused(data, g_KF + (size_t)c * NFFT, tid);
    __syncwarp();

    r16_inv(data, tw, 2, 1088, tid);
    bar128(tid);
    r16_inv(data, tw, 6, 1024, tid);
    __syncthreads();                        // i3 reads across all threads

    float bc = bias[c];
    float* o0 = out + ((size_t)(2*p)   * CC + c) * LL;
    float* o1 = out + ((size_t)(2*p+1) * CC + c) * LL;
    i3_store(data, tw, x0, x1, o0, o1, bc, tid);
}

extern "C" void kernel_launch(void* const* d_in, const int* in_sizes, int n_in,
                              void* d_out, int out_size) {
    const float* x      = (const float*)d_in[0];
    const float* bias   = (const float*)d_in[1];
    const float* z      = (const float*)d_in[2];
    const float* deltas = (const float*)d_in[3];
    const float* W0     = (const float*)d_in[4];
    const float* b0     = (const float*)d_in[5];
    const float* W1     = (const float*)d_in[6];
    const float* b1     = (const float*)d_in[7];
    const float* W2     = (const float*)d_in[8];
    const float* b2     = (const float*)d_in[9];
    const float* freq   = (const float*)d_in[10];
    const float* Wout   = (const float*)d_in[11];
    float* out = (float*)d_out;

    cudaFuncSetAttribute(kf_fft_kernel,   cudaFuncAttributeMaxDynamicSharedMemorySize, FFT_SMEM);
    cudaFuncSetAttribute(conv_fft_kernel, cudaFuncAttributeMaxDynamicSharedMemorySize, FFT_SMEM);

    mlp_hidden_kernel<<<LL / 32, 256>>>(z, W0, b0, W1, b1, W2, b2, freq);
    proj_kernel<<<dim3(LL / 32, 2), 256>>>(Wout, deltas);
    kf_fft_kernel<<<CC / 2, NT, FFT_SMEM>>>();
    conv_fft_kernel<<<dim3(CC, BB / 2), NT, FFT_SMEM>>>(x, bias, out);
}